// round 11
// baseline (speedup 1.0000x reference)
#include <cuda_runtime.h>
#include <cuda_bf16.h>
#include <math.h>

// ---------------------------------------------------------------------------
// Scratch (device globals — allocation-free per harness rules)
// ---------------------------------------------------------------------------
__device__ float g_x   [16384 * 256];
__device__ float g_y   [16384 * 256];
__device__ float g_qkv [3 * 16384 * 256];
__device__ float g_o   [16384 * 256];
__device__ float g_h1  [16384 * 128];
__device__ float g_pre [16384 * 1024];
__device__ float g_inT [16384 * 300];     // tf32-rounded inputs
__device__ float g_wtf [2042880];         // tf32-rounded weights (emb|qkvo|ff1|ff2)
__device__ float g_WihEncT[256 * 1024];   // (wih[:,256:512]).T, tf32-rounded
__device__ float g_WmR [128 * 2048];      // merged (wih[:,:256]+whh).T, [gb][sub][k]
__device__ float g_w1t [128 * 256];       // out_w1 transposed [h][k]
__device__ float g_g0  [1024];            // dec_h0 @ whh.T
__device__ float g_biasTot[1024];         // bih + bhh
__device__ float g_hbuf[2 * 32 * 256];
__device__ unsigned g_syncArr[8 * 64];    // 8 counters, 256B apart (zeroed in prep)

#define OFF_EMB  0
#define OFF_QKVO 76800
#define OFF_FF1  1649664
#define OFF_FF2  1846272

// ---------------------------------------------------------------------------
// tf32 / mma helpers
// ---------------------------------------------------------------------------
__device__ __forceinline__ unsigned f2tf(float f) {
    unsigned u;
    asm("cvt.rna.tf32.f32 %0, %1;" : "=r"(u) : "f"(f));
    return u;
}
__device__ __forceinline__ float tfv(float f) { return __uint_as_float(f2tf(f)); }

__device__ __forceinline__ void mma_tf32(float (&d)[4], const unsigned (&a)[4],
                                         const unsigned (&b)[2]) {
    asm volatile(
        "mma.sync.aligned.m16n8k8.row.col.f32.tf32.tf32.f32 "
        "{%0,%1,%2,%3}, {%4,%5,%6,%7}, {%8,%9}, {%0,%1,%2,%3};"
        : "+f"(d[0]), "+f"(d[1]), "+f"(d[2]), "+f"(d[3])
        : "r"(a[0]), "r"(a[1]), "r"(a[2]), "r"(a[3]), "r"(b[0]), "r"(b[1]));
}

__device__ __forceinline__ void cp16(unsigned dst, const void* src, int bytes) {
    asm volatile("cp.async.cg.shared.global [%0], [%1], 16, %2;"
                 :: "r"(dst), "l"(src), "r"(bytes));
}
__device__ __forceinline__ void cp_commit() {
    asm volatile("cp.async.commit_group;" ::: "memory");
}

// ---------------------------------------------------------------------------
// tf32 tensor-core GEMM (unchanged / passing).
// ---------------------------------------------------------------------------
#define GEMM_SMEM (3 * 128 * 20 * 4 + 3 * 16 * 136 * 4)

__global__ __launch_bounds__(256, 2) void gemm_tc(
    const float* __restrict__ A, const float* __restrict__ B,
    const float* __restrict__ bias, const float* __restrict__ res,
    float* __restrict__ C, int M, int N, int K, int relu, int outCvt,
    int nxPerMat, long bMatStride, long cMatStride, int biasMatStride)
{
    extern __shared__ unsigned dynsm[];
    unsigned (*As)[128][20] = (unsigned (*)[128][20])dynsm;
    unsigned (*Bs)[16][136] = (unsigned (*)[16][136])(dynsm + 3 * 128 * 20);

    const int tid = threadIdx.x;
    const int bx = blockIdx.x, by = blockIdx.y;
    const int mat = bx / nxPerMat;
    const int bxn = bx - mat * nxPerMat;

    const float* Bp    = B + (size_t)mat * bMatStride;
    const float* biasP = bias + (size_t)mat * biasMatStride;
    float*       Cp    = C + (size_t)mat * cMatStride;

    const float* Ablk = A + (size_t)(by * 128) * K;
    const float* Bblk = Bp + bxn * 128;

    const int lane = tid & 31, wid = tid >> 5;
    const int wm = wid >> 2, wn = wid & 3;
    const int gid = lane >> 2, tg = lane & 3;

    const int ar0 = tid >> 2, ac0 = (tid & 3) << 2;
    const int ar1 = ar0 + 64;
    const int bk0 = tid >> 5, bc0 = (tid & 31) << 2;
    const int bk1 = bk0 + 8;

    const unsigned sA = (unsigned)__cvta_generic_to_shared(&dynsm[0]);
    const unsigned sB = (unsigned)__cvta_generic_to_shared(&dynsm[3 * 128 * 20]);

    float acc[4][4][4];
#pragma unroll
    for (int mt = 0; mt < 4; mt++)
#pragma unroll
        for (int nt = 0; nt < 4; nt++)
#pragma unroll
            for (int i = 0; i < 4; i++) acc[mt][nt][i] = 0.f;

    auto issue = [&](int buf, int k0) {
        int c0 = k0 + ac0;
        int rem0 = K - c0;
        int by0 = rem0 >= 4 ? 16 : (rem0 > 0 ? rem0 * 4 : 0);
        cp16(sA + ((buf * 128 + ar0) * 20 + ac0) * 4,
             Ablk + (size_t)ar0 * K + (by0 ? c0 : 0), by0);
        cp16(sA + ((buf * 128 + ar1) * 20 + ac0) * 4,
             Ablk + (size_t)ar1 * K + (by0 ? c0 : 0), by0);
        int kr0 = k0 + bk0;
        int bb0 = (kr0 < K) ? 16 : 0;
        cp16(sB + ((buf * 16 + bk0) * 136 + bc0) * 4,
             Bblk + (size_t)(bb0 ? kr0 : 0) * N + bc0, bb0);
        int kr1 = k0 + bk1;
        int bb1 = (kr1 < K) ? 16 : 0;
        cp16(sB + ((buf * 16 + bk1) * 136 + bc0) * 4,
             Bblk + (size_t)(bb1 ? kr1 : 0) * N + bc0, bb1);
        cp_commit();
    };

    issue(0, 0);
    if (16 < K) issue(1, 16);

    int cur = 0;
    for (int k0 = 0; k0 < K; k0 += 16) {
        if (k0 + 16 < K) {
            asm volatile("cp.async.wait_group 1;" ::: "memory");
        } else {
            asm volatile("cp.async.wait_group 0;" ::: "memory");
        }
        __syncthreads();
        if (k0 + 32 < K) {
            int nb = cur + 2; if (nb >= 3) nb -= 3;
            issue(nb, k0 + 32);
        }

#pragma unroll
        for (int ks = 0; ks < 16; ks += 8) {
            unsigned a[4][4], b[4][2];
#pragma unroll
            for (int mt = 0; mt < 4; mt++) {
                int r = wm * 64 + mt * 16 + gid;
                a[mt][0] = As[cur][r][ks + tg];
                a[mt][1] = As[cur][r + 8][ks + tg];
                a[mt][2] = As[cur][r][ks + tg + 4];
                a[mt][3] = As[cur][r + 8][ks + tg + 4];
            }
#pragma unroll
            for (int nt = 0; nt < 4; nt++) {
                int cb = wn * 32 + nt * 8 + gid;
                b[nt][0] = Bs[cur][ks + tg][cb];
                b[nt][1] = Bs[cur][ks + tg + 4][cb];
            }
#pragma unroll
            for (int mt = 0; mt < 4; mt++)
#pragma unroll
                for (int nt = 0; nt < 4; nt++)
                    mma_tf32(acc[mt][nt], a[mt], b[nt]);
        }
        __syncthreads();
        cur = cur + 1; if (cur >= 3) cur -= 3;
    }

#pragma unroll
    for (int mt = 0; mt < 4; mt++) {
        int r0 = by * 128 + wm * 64 + mt * 16 + gid;
#pragma unroll
        for (int nt = 0; nt < 4; nt++) {
            int c0 = bxn * 128 + wn * 32 + nt * 8 + tg * 2;
            float bza = biasP[c0], bzb = biasP[c0 + 1];
            size_t off0 = (size_t)r0 * N + c0;
            size_t off1 = (size_t)(r0 + 8) * N + c0;
            float v0 = acc[mt][nt][0] + bza, v1 = acc[mt][nt][1] + bzb;
            float v2 = acc[mt][nt][2] + bza, v3 = acc[mt][nt][3] + bzb;
            if (res) {
                v0 += res[off0]; v1 += res[off0 + 1];
                v2 += res[off1]; v3 += res[off1 + 1];
            }
            if (relu) {
                v0 = fmaxf(v0, 0.f); v1 = fmaxf(v1, 0.f);
                v2 = fmaxf(v2, 0.f); v3 = fmaxf(v3, 0.f);
            }
            if (outCvt) {
                v0 = tfv(v0); v1 = tfv(v1); v2 = tfv(v2); v3 = tfv(v3);
            }
            *(float2*)(Cp + off0) = make_float2(v0, v1);
            *(float2*)(Cp + off1) = make_float2(v2, v3);
        }
    }
}

// ---------------------------------------------------------------------------
// LayerNorm (unchanged).
// ---------------------------------------------------------------------------
__global__ __launch_bounds__(256) void layernorm_k(
    const float* __restrict__ x, const float* __restrict__ g,
    const float* __restrict__ b, float* __restrict__ y)
{
    int tid = threadIdx.x;
    int lane = tid & 31;
    int row = blockIdx.x * 8 + (tid >> 5);

    const float4* xr = (const float4*)(x + (size_t)row * 256);
    float4 v0 = xr[lane], v1 = xr[lane + 32];

    float s = v0.x + v0.y + v0.z + v0.w + v1.x + v1.y + v1.z + v1.w;
#pragma unroll
    for (int o = 16; o > 0; o >>= 1) s += __shfl_xor_sync(0xffffffffu, s, o);
    float mean = s * (1.f / 256.f);

    float4 d0 = make_float4(v0.x - mean, v0.y - mean, v0.z - mean, v0.w - mean);
    float4 d1 = make_float4(v1.x - mean, v1.y - mean, v1.z - mean, v1.w - mean);
    float sq = d0.x * d0.x + d0.y * d0.y + d0.z * d0.z + d0.w * d0.w
             + d1.x * d1.x + d1.y * d1.y + d1.z * d1.z + d1.w * d1.w;
#pragma unroll
    for (int o = 16; o > 0; o >>= 1) sq += __shfl_xor_sync(0xffffffffu, sq, o);
    float var = sq * (1.f / 255.f);
    float r = 1.f / (sqrtf(var) + 1e-6f);

    const float4* g4 = (const float4*)g;
    const float4* b4 = (const float4*)b;
    float4 gg0 = g4[lane], gg1 = g4[lane + 32];
    float4 bb0 = b4[lane], bb1 = b4[lane + 32];

    float4 o0, o1;
    o0.x = tfv(gg0.x * d0.x * r + bb0.x); o0.y = tfv(gg0.y * d0.y * r + bb0.y);
    o0.z = tfv(gg0.z * d0.z * r + bb0.z); o0.w = tfv(gg0.w * d0.w * r + bb0.w);
    o1.x = tfv(gg1.x * d1.x * r + bb1.x); o1.y = tfv(gg1.y * d1.y * r + bb1.y);
    o1.z = tfv(gg1.z * d1.z * r + bb1.z); o1.w = tfv(gg1.w * d1.w * r + bb1.w);

    float4* yr = (float4*)(y + (size_t)row * 256);
    yr[lane] = o0;
    yr[lane + 32] = o1;
}

// ---------------------------------------------------------------------------
// Tensor-core flash attention (unchanged).
// ---------------------------------------------------------------------------
__global__ __launch_bounds__(256, 2) void attn_tc(
    const float* __restrict__ Q, const float* __restrict__ K,
    const float* __restrict__ V, const float* __restrict__ mask,
    float* __restrict__ O)
{
    extern __shared__ unsigned smu[];
    unsigned* Ks = smu;                        // [128][44]
    unsigned* Vs = smu + 128 * 44;             // [128][40]
    unsigned* Ps = smu + 128 * 44 + 128 * 40;  // [128][132]

    const int qt = blockIdx.x;
    const int bh = blockIdx.y;
    const int b = bh >> 3, h = bh & 7;
    const int tid = threadIdx.x;
    const int w = tid >> 5, lane = tid & 31;
    const int gid = lane >> 2, tg = lane & 3;

    const int r0 = w * 16 + gid;
    const int r1 = r0 + 8;
    const size_t qbase = ((size_t)(b * 512 + qt * 128)) * 256 + h * 32;
    const float scale = 0.17677669529663689f;

    unsigned aQ[4][4];
#pragma unroll
    for (int ks = 0; ks < 4; ks++) {
        aQ[ks][0] = f2tf(Q[qbase + (size_t)r0 * 256 + ks * 8 + tg] * scale);
        aQ[ks][1] = f2tf(Q[qbase + (size_t)r1 * 256 + ks * 8 + tg] * scale);
        aQ[ks][2] = f2tf(Q[qbase + (size_t)r0 * 256 + ks * 8 + tg + 4] * scale);
        aQ[ks][3] = f2tf(Q[qbase + (size_t)r1 * 256 + ks * 8 + tg + 4] * scale);
    }
    const bool mz0 = (mask[b * 512 + qt * 128 + r0] == 0.f);
    const bool mz1 = (mask[b * 512 + qt * 128 + r1] == 0.f);

    float m0 = -1e30f, m1 = -1e30f, l0 = 0.f, l1 = 0.f;
    float o[4][4];
#pragma unroll
    for (int nt = 0; nt < 4; nt++)
#pragma unroll
        for (int i = 0; i < 4; i++) o[nt][i] = 0.f;

    for (int kc = 0; kc < 4; kc++) {
        __syncthreads();
        const size_t kvbase = ((size_t)(b * 512 + kc * 128)) * 256 + h * 32;
        for (int idx = tid; idx < 1024; idx += 256) {
            int key = idx >> 3, d4 = idx & 7;
            const uint4* ks4 = (const uint4*)(K + kvbase + (size_t)key * 256) + d4;
            const uint4* vs4 = (const uint4*)(V + kvbase + (size_t)key * 256) + d4;
            *(uint4*)(Ks + key * 44 + d4 * 4) = *ks4;
            *(uint4*)(Vs + key * 40 + d4 * 4) = *vs4;
        }
        __syncthreads();

        float s[16][4];
#pragma unroll
        for (int nt = 0; nt < 16; nt++) {
            s[nt][0] = s[nt][1] = s[nt][2] = s[nt][3] = 0.f;
            const unsigned* kp = Ks + (nt * 8 + gid) * 44;
#pragma unroll
            for (int ks = 0; ks < 4; ks++) {
                unsigned bk[2] = { kp[ks * 8 + tg], kp[ks * 8 + tg + 4] };
                mma_tf32(s[nt], aQ[ks], bk);
            }
        }
        if (mz0) {
#pragma unroll
            for (int nt = 0; nt < 16; nt++) { s[nt][0] = -1e9f; s[nt][1] = -1e9f; }
        }
        if (mz1) {
#pragma unroll
            for (int nt = 0; nt < 16; nt++) { s[nt][2] = -1e9f; s[nt][3] = -1e9f; }
        }

        float rm0 = -1e30f, rm1 = -1e30f;
#pragma unroll
        for (int nt = 0; nt < 16; nt++) {
            rm0 = fmaxf(rm0, fmaxf(s[nt][0], s[nt][1]));
            rm1 = fmaxf(rm1, fmaxf(s[nt][2], s[nt][3]));
        }
        rm0 = fmaxf(rm0, __shfl_xor_sync(0xffffffffu, rm0, 1));
        rm0 = fmaxf(rm0, __shfl_xor_sync(0xffffffffu, rm0, 2));
        rm1 = fmaxf(rm1, __shfl_xor_sync(0xffffffffu, rm1, 1));
        rm1 = fmaxf(rm1, __shfl_xor_sync(0xffffffffu, rm1, 2));
        float mn0 = fmaxf(m0, rm0), mn1 = fmaxf(m1, rm1);
        float c0 = __expf(m0 - mn0), c1 = __expf(m1 - mn1);
        m0 = mn0; m1 = mn1;

        float ps0 = 0.f, ps1 = 0.f;
        unsigned* pr0 = Ps + r0 * 132;
        unsigned* pr1 = Ps + r1 * 132;
#pragma unroll
        for (int nt = 0; nt < 16; nt++) {
            float p00 = __expf(s[nt][0] - mn0), p01 = __expf(s[nt][1] - mn0);
            float p10 = __expf(s[nt][2] - mn1), p11 = __expf(s[nt][3] - mn1);
            ps0 += p00 + p01;
            ps1 += p10 + p11;
            int cc = nt * 8 + 2 * tg;
            pr0[cc] = f2tf(p00); pr0[cc + 1] = f2tf(p01);
            pr1[cc] = f2tf(p10); pr1[cc + 1] = f2tf(p11);
        }
        ps0 += __shfl_xor_sync(0xffffffffu, ps0, 1);
        ps0 += __shfl_xor_sync(0xffffffffu, ps0, 2);
        ps1 += __shfl_xor_sync(0xffffffffu, ps1, 1);
        ps1 += __shfl_xor_sync(0xffffffffu, ps1, 2);
        l0 = l0 * c0 + ps0;
        l1 = l1 * c1 + ps1;
#pragma unroll
        for (int nt = 0; nt < 4; nt++) {
            o[nt][0] *= c0; o[nt][1] *= c0;
            o[nt][2] *= c1; o[nt][3] *= c1;
        }
        __syncwarp();

#pragma unroll
        for (int ks = 0; ks < 16; ks++) {
            unsigned aP[4] = { pr0[ks * 8 + tg], pr1[ks * 8 + tg],
                               pr0[ks * 8 + tg + 4], pr1[ks * 8 + tg + 4] };
#pragma unroll
            for (int nt = 0; nt < 4; nt++) {
                const unsigned* vp = Vs + nt * 8 + gid;
                unsigned bv[2] = { vp[(ks * 8 + tg) * 40], vp[(ks * 8 + tg + 4) * 40] };
                mma_tf32(o[nt], aP, bv);
            }
        }
    }

    float inv0 = 1.f / l0, inv1 = 1.f / l1;
    float* Or0 = O + qbase + (size_t)r0 * 256;
    float* Or1 = O + qbase + (size_t)r1 * 256;
#pragma unroll
    for (int nt = 0; nt < 4; nt++) {
        int cc = nt * 8 + 2 * tg;
        Or0[cc]     = tfv(o[nt][0] * inv0);
        Or0[cc + 1] = tfv(o[nt][1] * inv0);
        Or1[cc]     = tfv(o[nt][2] * inv1);
        Or1[cc + 1] = tfv(o[nt][3] * inv1);
    }
}

// ---------------------------------------------------------------------------
// Weight/input pre-conversion to tf32-rounded fp32 values (unchanged)
// ---------------------------------------------------------------------------
__global__ __launch_bounds__(256) void cvtw_k(
    const float* __restrict__ inputs, const float* __restrict__ emb,
    const float* __restrict__ qkvo, const float* __restrict__ f1,
    const float* __restrict__ f2, float* __restrict__ inT,
    float* __restrict__ wtf)
{
    int idx = blockIdx.x * 256 + threadIdx.x;
    if (idx < 4915200) inT[idx] = tfv(inputs[idx]);
    if (idx < 2042880) {
        float v;
        if (idx < OFF_QKVO)      v = emb[idx - OFF_EMB];
        else if (idx < OFF_FF1)  v = qkvo[idx - OFF_QKVO];
        else if (idx < OFF_FF2)  v = f1[idx - OFF_FF1];
        else                     v = f2[idx - OFF_FF2];
        wtf[idx] = tfv(v);
    }
}

// ---------------------------------------------------------------------------
// LSTM prep (zeroes the 8 distributed barrier counters).
// ---------------------------------------------------------------------------
__global__ __launch_bounds__(256) void lstm_prep_k(
    const float* __restrict__ wih, const float* __restrict__ whh,
    const float* __restrict__ bih, const float* __restrict__ bhh,
    const float* __restrict__ dec_h0, const float* __restrict__ out_w1,
    float* __restrict__ WihEncT, float* __restrict__ WmR,
    float* __restrict__ w1t, float* __restrict__ g0,
    float* __restrict__ biasTot, unsigned* __restrict__ syncArr)
{
    int idx = blockIdx.x * 256 + threadIdx.x;
    if (idx < 8) syncArr[idx * 64] = 0u;
    if (idx < 262144) {
        int k = idx >> 10, n = idx & 1023;
        WihEncT[idx] = tfv(wih[(size_t)n * 512 + 256 + k]);

        int gb = idx >> 11;          // 0..127
        int r = idx & 2047;
        int sub = r >> 8;            // 0..7
        int kk = r & 255;
        int g = sub & 3, el = sub >> 2;
        int col = g * 256 + gb * 2 + el;
        WmR[idx] = wih[(size_t)col * 512 + kk] + whh[(size_t)col * 256 + kk];
    }
    if (idx < 32768) {
        int h = idx >> 8, k = idx & 255;
        w1t[idx] = out_w1[(size_t)k * 128 + h];
    }
    if (idx < 1024) {
        float a = 0.f;
        for (int k = 0; k < 256; k++) a = fmaf(dec_h0[k], whh[(size_t)idx * 256 + k], a);
        g0[idx] = a;
        biasTot[idx] = bih[idx] + bhh[idx];
    }
}

// ---------------------------------------------------------------------------
// Persistent LSTM: 144 blocks (128 gate + 16 MLP). Single change vs R10:
// distributed 8-counter grid barrier (18 blocks/counter) — kills the
// single-address L2 atomic serialization (~3900 cyc -> ~800 cyc per step).
// ---------------------------------------------------------------------------
__device__ __forceinline__ float sigf(float x) { return 1.f / (1.f + __expf(-x)); }

__device__ __forceinline__ void grid_bar(unsigned* syncArr, unsigned tstep) {
    __threadfence();
    __syncthreads();
    if (threadIdx.x == 0)
        atomicAdd(syncArr + (blockIdx.x & 7) * 64, 1u);
    if (threadIdx.x < 8) {
        unsigned tgt = tstep * 18u;
        while (*(volatile unsigned*)(syncArr + threadIdx.x * 64) < tgt) { }
        __threadfence();
    }
    __syncthreads();
}

__global__ __launch_bounds__(256, 1) void lstm_persist_k(
    const float* __restrict__ pre, const float* __restrict__ WmR,
    const float* __restrict__ w1t, const float* __restrict__ g0,
    const float* __restrict__ dec_c0,
    const float* __restrict__ b1, const float* __restrict__ w2,
    const float* __restrict__ b2, const float* __restrict__ mask,
    float* __restrict__ hbuf, unsigned* __restrict__ syncArr,
    float* __restrict__ out)
{
    extern __shared__ float sm[];
    const int tid = threadIdx.x;

    if (blockIdx.x < 128) {
        // -------- gate block: 2 e-cols, one full dot per thread --------
        const int gb = blockIdx.x;
        const int b = tid >> 3;          // batch 0..31
        const int sub = tid & 7;         // (el<<2)|g
        const int g = sub & 3;
        const int el = sub >> 2;
        const int e = gb * 2 + el;
        const int col = g * 256 + e;
        const int lane = tid & 31;
        const int base = lane & ~3;      // lane of g==0 in this quad

        float* ws = sm;                       // [8][260] floats (padded)
        float4* hs4 = (float4*)(sm + 2080);   // [32][65] float4 (padded rows)

        for (int i = tid; i < 2048; i += 256) {
            int ss = i >> 8, kk = i & 255;
            ws[ss * 260 + kk] = WmR[(size_t)gb * 2048 + i];
        }
        const float4* wp = (const float4*)(ws + sub * 260);

        float c = (g == 0) ? dec_c0[e] : 0.f;

        for (int t = 0; t < 512; ++t) {
            float gate;
            if (t == 0) {
                gate = pre[(size_t)b * 524288 + col] + g0[col];
            } else {
                float prv = __ldg(pre + ((size_t)b * 512 + t) * 1024 + col);

                const float4* hsrc = (const float4*)(hbuf + (t & 1) * 8192);
                for (int j = tid; j < 2048; j += 256) {
                    int row = j >> 6, cc = j & 63;
                    hs4[row * 65 + cc] = __ldcg(hsrc + j);
                }
                __syncthreads();

                const float4* hp = hs4 + b * 65;
                float a0 = 0.f, a1 = 0.f, a2 = 0.f, a3 = 0.f;
#pragma unroll 8
                for (int kk = 0; kk < 64; kk += 4) {
                    float4 h0 = hp[kk],     w0 = wp[kk];
                    float4 h1 = hp[kk + 1], w1v = wp[kk + 1];
                    float4 h2 = hp[kk + 2], w2v = wp[kk + 2];
                    float4 h3 = hp[kk + 3], w3v = wp[kk + 3];
                    a0 = fmaf(h0.x, w0.x, fmaf(h0.y, w0.y, fmaf(h0.z, w0.z, fmaf(h0.w, w0.w, a0))));
                    a1 = fmaf(h1.x, w1v.x, fmaf(h1.y, w1v.y, fmaf(h1.z, w1v.z, fmaf(h1.w, w1v.w, a1))));
                    a2 = fmaf(h2.x, w2v.x, fmaf(h2.y, w2v.y, fmaf(h2.z, w2v.z, fmaf(h2.w, w2v.w, a2))));
                    a3 = fmaf(h3.x, w3v.x, fmaf(h3.y, w3v.y, fmaf(h3.z, w3v.z, fmaf(h3.w, w3v.w, a3))));
                }
                gate = (a0 + a1) + (a2 + a3) + prv;
                __syncthreads();
            }

            float gi = __shfl_sync(0xffffffffu, gate, base + 0);
            float gf = __shfl_sync(0xffffffffu, gate, base + 1);
            float gg = __shfl_sync(0xffffffffu, gate, base + 2);
            float go = __shfl_sync(0xffffffffu, gate, base + 3);
            if (g == 0) {
                float cn = sigf(gf) * c + sigf(gi) * tanhf(gg);
                float hn = sigf(go) * tanhf(cn);
                c = cn;
                __stcg(hbuf + ((t + 1) & 1) * 8192 + b * 256 + e, hn);
            }
            grid_bar(syncArr, (unsigned)(t + 1));
        }
    } else {
        // -------- MLP block: 2 batches, lagged output head --------
        const int mb = blockIdx.x - 128;
        const int bat = tid >> 7;
        const int ho = tid & 127;
        float* w1s  = sm;                // [128][260] floats
        float* hrow = sm + 33280;        // [2][256]
        float* red  = sm + 33792;        // [8]

        for (int i = tid; i < 8192; i += 256) {
            int h = i >> 6, k4 = i & 63;
            ((float4*)w1s)[h * 65 + k4] = ((const float4*)w1t)[i];
        }
        float w2v = w2[ho];
        float b1v = b1[ho];
        float b2v = b2[0];

        for (int t = 0; t <= 512; ++t) {
            if (t >= 1) {
                for (int i = tid; i < 512; i += 256) {
                    int bb = i >> 8, k = i & 255;
                    hrow[bb * 256 + k] =
                        __ldcg(hbuf + (t & 1) * 8192 + (mb * 2 + bb) * 256 + k);
                }
                __syncthreads();

                float a = b1v;
                const float4* h4 = (const float4*)(hrow + bat * 256);
                const float4* w4 = (const float4*)(w1s + ho * 260);
#pragma unroll 16
                for (int kk = 0; kk < 64; kk++) {
                    float4 hv = h4[kk];
                    float4 wv = w4[kk];
                    a = fmaf(hv.x, wv.x, fmaf(hv.y, wv.y, fmaf(hv.z, wv.z, fmaf(hv.w, wv.w, a))));
                }
                float contrib = fmaxf(a, 0.f) * w2v;
#pragma unroll
                for (int o = 16; o > 0; o >>= 1)
                    contrib += __shfl_down_sync(0xffffffffu, contrib, o);
                if ((tid & 31) == 0) red[tid >> 5] = contrib;
                __syncthreads();
                if (tid == 0) {
                    int bidx = mb * 2;
                    float pp = red[0] + red[1] + red[2] + red[3] + b2v;
                    out[bidx * 512 + (t - 1)] = pp * mask[bidx * 512 + (t - 1)];
                }
                if (tid == 128) {
                    int bidx = mb * 2 + 1;
                    float pp = red[4] + red[5] + red[6] + red[7] + b2v;
                    out[bidx * 512 + (t - 1)] = pp * mask[bidx * 512 + (t - 1)];
                }
                __syncthreads();
            }
            if (t < 512) grid_bar(syncArr, (unsigned)(t + 1));
        }
    }
}

// ---------------------------------------------------------------------------
// Launcher
// ---------------------------------------------------------------------------
extern "C" void kernel_launch(void* const* d_in, const int* in_sizes, int n_in,
                              void* d_out, int out_size)
{
    const float* inputs   = (const float*)d_in[0];
    const float* mask     = (const float*)d_in[1];
    /* d_in[2] = lengths (unused) */
    const float* embed_w  = (const float*)d_in[3];
    const float* embed_b  = (const float*)d_in[4];
    const float* qkvo_w   = (const float*)d_in[5];
    const float* qkvo_b   = (const float*)d_in[6];
    const float* ln_g     = (const float*)d_in[7];
    const float* ln_b     = (const float*)d_in[8];
    const float* ff_w1    = (const float*)d_in[9];
    const float* ff_b1    = (const float*)d_in[10];
    const float* ff_w2    = (const float*)d_in[11];
    const float* ff_b2    = (const float*)d_in[12];
    const float* enc_ln_g = (const float*)d_in[13];
    const float* enc_ln_b = (const float*)d_in[14];
    const float* wih      = (const float*)d_in[15];
    const float* whh      = (const float*)d_in[16];
    const float* bih      = (const float*)d_in[17];
    const float* bhh      = (const float*)d_in[18];
    const float* dec_h0   = (const float*)d_in[19];
    const float* dec_c0   = (const float*)d_in[20];
    const float* out_w1   = (const float*)d_in[21];
    const float* out_b1   = (const float*)d_in[22];
    const float* out_w2   = (const float*)d_in[23];
    const float* out_b2   = (const float*)d_in[24];
    float* out = (float*)d_out;
    (void)in_sizes; (void)n_in; (void)out_size;

    float *px, *py, *pqkv, *po, *ph1, *ppre, *pinT, *pwtf, *pWET, *pWmR, *pw1t,
          *pg0, *pbt, *phb;
    unsigned* psync;
    cudaGetSymbolAddress((void**)&px,    g_x);
    cudaGetSymbolAddress((void**)&py,    g_y);
    cudaGetSymbolAddress((void**)&pqkv,  g_qkv);
    cudaGetSymbolAddress((void**)&po,    g_o);
    cudaGetSymbolAddress((void**)&ph1,   g_h1);
    cudaGetSymbolAddress((void**)&ppre,  g_pre);
    cudaGetSymbolAddress((void**)&pinT,  g_inT);
    cudaGetSymbolAddress((void**)&pwtf,  g_wtf);
    cudaGetSymbolAddress((void**)&pWET,  g_WihEncT);
    cudaGetSymbolAddress((void**)&pWmR,  g_WmR);
    cudaGetSymbolAddress((void**)&pw1t,  g_w1t);
    cudaGetSymbolAddress((void**)&pg0,   g_g0);
    cudaGetSymbolAddress((void**)&pbt,   g_biasTot);
    cudaGetSymbolAddress((void**)&phb,   g_hbuf);
    cudaGetSymbolAddress((void**)&psync, g_syncArr);

    cudaFuncSetAttribute(gemm_tc, cudaFuncAttributeMaxDynamicSharedMemorySize, GEMM_SMEM);
    cudaFuncSetAttribute(attn_tc, cudaFuncAttributeMaxDynamicSharedMemorySize, 110592);
    cudaFuncSetAttribute(lstm_persist_k, cudaFuncAttributeMaxDynamicSharedMemorySize, 137216);

    const int M = 16384;
    const long QKV_C = 16384L * 256;

    // prep: tf32 conversions + LSTM weights + barrier reset
    cvtw_k<<<19200, 256>>>(inputs, embed_w, qkvo_w, ff_w1, ff_w2, pinT, pwtf);
    lstm_prep_k<<<1024, 256>>>(wih, whh, bih, bhh, dec_h0, out_w1,
                               pWET, pWmR, pw1t, pg0, pbt, psync);

    // Embed (K=300)
    gemm_tc<<<dim3(2, 128), 256, GEMM_SMEM>>>(pinT, pwtf + OFF_EMB, embed_b,
                                              nullptr, px,
                                              M, 256, 300, 0, 0, 2, 0, 0, 0);

    // Transformer layers
    for (int l = 0; l < 6; l++) {
        const float* Wq = pwtf + OFF_QKVO + (size_t)(l * 4) * 65536;
        const float* Wo = pwtf + OFF_QKVO + (size_t)(l * 4 + 3) * 65536;
        const float* bq = qkvo_b + (l * 4) * 256;
        const float* bo = qkvo_b + (l * 4 + 3) * 256;

        layernorm_k<<<2048, 256>>>(px, ln_g + l * 512, ln_b + l * 512, py);
        gemm_tc<<<dim3(6, 128), 256, GEMM_SMEM>>>(py, Wq, bq, nullptr, pqkv,
                                                  M, 256, 256, 0, 1,
                                                  2, 65536, QKV_C, 256);
        attn_tc<<<dim3(4, 256), 256, 110592>>>(pqkv, pqkv + QKV_C,
                                               pqkv + 2 * QKV_C, mask, po);
        gemm_tc<<<dim3(2, 128), 256, GEMM_SMEM>>>(po, Wo, bo, px, px,
                                                  M, 256, 256, 0, 0, 2, 0, 0, 0);

        layernorm_k<<<2048, 256>>>(px, ln_g + l * 512 + 256, ln_b + l * 512 + 256, py);
        gemm_tc<<<dim3(1, 128), 256, GEMM_SMEM>>>(py, pwtf + OFF_FF1 + (size_t)l * 32768,
                                                  ff_b1 + l * 128, nullptr, ph1,
                                                  M, 128, 256, 1, 1, 1, 0, 0, 0);
        gemm_tc<<<dim3(2, 128), 256, GEMM_SMEM>>>(ph1, pwtf + OFF_FF2 + (size_t)l * 32768,
                                                  ff_b2 + l * 256, px, px,
                                                  M, 256, 128, 0, 0, 2, 0, 0, 0);
    }

    // Encoder LN -> enc (in py, tf32-rounded)
    layernorm_k<<<2048, 256>>>(px, enc_ln_g, enc_ln_b, py);

    // pre = enc @ wih[:,256:].T + (bih+bhh)
    gemm_tc<<<dim3(8, 128), 256, GEMM_SMEM>>>(py, pWET, pbt, nullptr, ppre,
                                              M, 1024, 256, 0, 0, 8, 0, 0, 0);

    // Persistent LSTM scan + output head (single launch, 144 blocks)
    lstm_persist_k<<<144, 256, 137216>>>(ppre, pWmR, pw1t, pg0, dec_c0,
                                         out_b1, out_w2, out_b2, mask,
                                         phb, psync, out);
}

// round 12
// speedup vs baseline: 1.1684x; 1.1684x over previous
#include <cuda_runtime.h>
#include <cuda_bf16.h>
#include <math.h>

// ---------------------------------------------------------------------------
// Scratch (device globals — allocation-free per harness rules)
// ---------------------------------------------------------------------------
__device__ float g_x   [16384 * 256];
__device__ float g_y   [16384 * 256];
__device__ float g_qkv [3 * 16384 * 256];
__device__ float g_o   [16384 * 256];
__device__ float g_h1  [16384 * 128];
__device__ float g_pre [16384 * 1024];
__device__ float g_inT [16384 * 300];     // tf32-rounded inputs
__device__ float g_wtf [2042880];         // tf32-rounded weights (emb|qkvo|ff1|ff2)
__device__ float g_WihEncT[256 * 1024];   // (wih[:,256:512]).T, tf32-rounded
__device__ float g_WmR [8 * 128 * 256];   // merged (wih+whh).T, [j][lc][k]
__device__ float g_w1t [128 * 256];       // out_w1 transposed [h][k]
__device__ float g_g0  [1024];            // dec_h0 @ whh.T
__device__ float g_biasTot[1024];         // bih + bhh
__device__ float g_hbuf[2 * 32 * 256];
__device__ unsigned g_syncArr[16 * 64];   // 16 group counters, 256B apart

#define OFF_EMB  0
#define OFF_QKVO 76800
#define OFF_FF1  1649664
#define OFF_FF2  1846272

// ---------------------------------------------------------------------------
// tf32 / mma helpers
// ---------------------------------------------------------------------------
__device__ __forceinline__ unsigned f2tf(float f) {
    unsigned u;
    asm("cvt.rna.tf32.f32 %0, %1;" : "=r"(u) : "f"(f));
    return u;
}
__device__ __forceinline__ float tfv(float f) { return __uint_as_float(f2tf(f)); }

__device__ __forceinline__ void mma_tf32(float (&d)[4], const unsigned (&a)[4],
                                         const unsigned (&b)[2]) {
    asm volatile(
        "mma.sync.aligned.m16n8k8.row.col.f32.tf32.tf32.f32 "
        "{%0,%1,%2,%3}, {%4,%5,%6,%7}, {%8,%9}, {%0,%1,%2,%3};"
        : "+f"(d[0]), "+f"(d[1]), "+f"(d[2]), "+f"(d[3])
        : "r"(a[0]), "r"(a[1]), "r"(a[2]), "r"(a[3]), "r"(b[0]), "r"(b[1]));
}

__device__ __forceinline__ void cp16(unsigned dst, const void* src, int bytes) {
    asm volatile("cp.async.cg.shared.global [%0], [%1], 16, %2;"
                 :: "r"(dst), "l"(src), "r"(bytes));
}
__device__ __forceinline__ void cp_commit() {
    asm volatile("cp.async.commit_group;" ::: "memory");
}

// ---------------------------------------------------------------------------
// tf32 tensor-core GEMM (unchanged / passing).
// ---------------------------------------------------------------------------
#define GEMM_SMEM (3 * 128 * 20 * 4 + 3 * 16 * 136 * 4)

__global__ __launch_bounds__(256, 2) void gemm_tc(
    const float* __restrict__ A, const float* __restrict__ B,
    const float* __restrict__ bias, const float* __restrict__ res,
    float* __restrict__ C, int M, int N, int K, int relu, int outCvt,
    int nxPerMat, long bMatStride, long cMatStride, int biasMatStride)
{
    extern __shared__ unsigned dynsm[];
    unsigned (*As)[128][20] = (unsigned (*)[128][20])dynsm;
    unsigned (*Bs)[16][136] = (unsigned (*)[16][136])(dynsm + 3 * 128 * 20);

    const int tid = threadIdx.x;
    const int bx = blockIdx.x, by = blockIdx.y;
    const int mat = bx / nxPerMat;
    const int bxn = bx - mat * nxPerMat;

    const float* Bp    = B + (size_t)mat * bMatStride;
    const float* biasP = bias + (size_t)mat * biasMatStride;
    float*       Cp    = C + (size_t)mat * cMatStride;

    const float* Ablk = A + (size_t)(by * 128) * K;
    const float* Bblk = Bp + bxn * 128;

    const int lane = tid & 31, wid = tid >> 5;
    const int wm = wid >> 2, wn = wid & 3;
    const int gid = lane >> 2, tg = lane & 3;

    const int ar0 = tid >> 2, ac0 = (tid & 3) << 2;
    const int ar1 = ar0 + 64;
    const int bk0 = tid >> 5, bc0 = (tid & 31) << 2;
    const int bk1 = bk0 + 8;

    const unsigned sA = (unsigned)__cvta_generic_to_shared(&dynsm[0]);
    const unsigned sB = (unsigned)__cvta_generic_to_shared(&dynsm[3 * 128 * 20]);

    float acc[4][4][4];
#pragma unroll
    for (int mt = 0; mt < 4; mt++)
#pragma unroll
        for (int nt = 0; nt < 4; nt++)
#pragma unroll
            for (int i = 0; i < 4; i++) acc[mt][nt][i] = 0.f;

    auto issue = [&](int buf, int k0) {
        int c0 = k0 + ac0;
        int rem0 = K - c0;
        int by0 = rem0 >= 4 ? 16 : (rem0 > 0 ? rem0 * 4 : 0);
        cp16(sA + ((buf * 128 + ar0) * 20 + ac0) * 4,
             Ablk + (size_t)ar0 * K + (by0 ? c0 : 0), by0);
        cp16(sA + ((buf * 128 + ar1) * 20 + ac0) * 4,
             Ablk + (size_t)ar1 * K + (by0 ? c0 : 0), by0);
        int kr0 = k0 + bk0;
        int bb0 = (kr0 < K) ? 16 : 0;
        cp16(sB + ((buf * 16 + bk0) * 136 + bc0) * 4,
             Bblk + (size_t)(bb0 ? kr0 : 0) * N + bc0, bb0);
        int kr1 = k0 + bk1;
        int bb1 = (kr1 < K) ? 16 : 0;
        cp16(sB + ((buf * 16 + bk1) * 136 + bc0) * 4,
             Bblk + (size_t)(bb1 ? kr1 : 0) * N + bc0, bb1);
        cp_commit();
    };

    issue(0, 0);
    if (16 < K) issue(1, 16);

    int cur = 0;
    for (int k0 = 0; k0 < K; k0 += 16) {
        if (k0 + 16 < K) {
            asm volatile("cp.async.wait_group 1;" ::: "memory");
        } else {
            asm volatile("cp.async.wait_group 0;" ::: "memory");
        }
        __syncthreads();
        if (k0 + 32 < K) {
            int nb = cur + 2; if (nb >= 3) nb -= 3;
            issue(nb, k0 + 32);
        }

#pragma unroll
        for (int ks = 0; ks < 16; ks += 8) {
            unsigned a[4][4], b[4][2];
#pragma unroll
            for (int mt = 0; mt < 4; mt++) {
                int r = wm * 64 + mt * 16 + gid;
                a[mt][0] = As[cur][r][ks + tg];
                a[mt][1] = As[cur][r + 8][ks + tg];
                a[mt][2] = As[cur][r][ks + tg + 4];
                a[mt][3] = As[cur][r + 8][ks + tg + 4];
            }
#pragma unroll
            for (int nt = 0; nt < 4; nt++) {
                int cb = wn * 32 + nt * 8 + gid;
                b[nt][0] = Bs[cur][ks + tg][cb];
                b[nt][1] = Bs[cur][ks + tg + 4][cb];
            }
#pragma unroll
            for (int mt = 0; mt < 4; mt++)
#pragma unroll
                for (int nt = 0; nt < 4; nt++)
                    mma_tf32(acc[mt][nt], a[mt], b[nt]);
        }
        __syncthreads();
        cur = cur + 1; if (cur >= 3) cur -= 3;
    }

#pragma unroll
    for (int mt = 0; mt < 4; mt++) {
        int r0 = by * 128 + wm * 64 + mt * 16 + gid;
#pragma unroll
        for (int nt = 0; nt < 4; nt++) {
            int c0 = bxn * 128 + wn * 32 + nt * 8 + tg * 2;
            float bza = biasP[c0], bzb = biasP[c0 + 1];
            size_t off0 = (size_t)r0 * N + c0;
            size_t off1 = (size_t)(r0 + 8) * N + c0;
            float v0 = acc[mt][nt][0] + bza, v1 = acc[mt][nt][1] + bzb;
            float v2 = acc[mt][nt][2] + bza, v3 = acc[mt][nt][3] + bzb;
            if (res) {
                v0 += res[off0]; v1 += res[off0 + 1];
                v2 += res[off1]; v3 += res[off1 + 1];
            }
            if (relu) {
                v0 = fmaxf(v0, 0.f); v1 = fmaxf(v1, 0.f);
                v2 = fmaxf(v2, 0.f); v3 = fmaxf(v3, 0.f);
            }
            if (outCvt) {
                v0 = tfv(v0); v1 = tfv(v1); v2 = tfv(v2); v3 = tfv(v3);
            }
            *(float2*)(Cp + off0) = make_float2(v0, v1);
            *(float2*)(Cp + off1) = make_float2(v2, v3);
        }
    }
}

// ---------------------------------------------------------------------------
// LayerNorm (unchanged).
// ---------------------------------------------------------------------------
__global__ __launch_bounds__(256) void layernorm_k(
    const float* __restrict__ x, const float* __restrict__ g,
    const float* __restrict__ b, float* __restrict__ y)
{
    int tid = threadIdx.x;
    int lane = tid & 31;
    int row = blockIdx.x * 8 + (tid >> 5);

    const float4* xr = (const float4*)(x + (size_t)row * 256);
    float4 v0 = xr[lane], v1 = xr[lane + 32];

    float s = v0.x + v0.y + v0.z + v0.w + v1.x + v1.y + v1.z + v1.w;
#pragma unroll
    for (int o = 16; o > 0; o >>= 1) s += __shfl_xor_sync(0xffffffffu, s, o);
    float mean = s * (1.f / 256.f);

    float4 d0 = make_float4(v0.x - mean, v0.y - mean, v0.z - mean, v0.w - mean);
    float4 d1 = make_float4(v1.x - mean, v1.y - mean, v1.z - mean, v1.w - mean);
    float sq = d0.x * d0.x + d0.y * d0.y + d0.z * d0.z + d0.w * d0.w
             + d1.x * d1.x + d1.y * d1.y + d1.z * d1.z + d1.w * d1.w;
#pragma unroll
    for (int o = 16; o > 0; o >>= 1) sq += __shfl_xor_sync(0xffffffffu, sq, o);
    float var = sq * (1.f / 255.f);
    float r = 1.f / (sqrtf(var) + 1e-6f);

    const float4* g4 = (const float4*)g;
    const float4* b4 = (const float4*)b;
    float4 gg0 = g4[lane], gg1 = g4[lane + 32];
    float4 bb0 = b4[lane], bb1 = b4[lane + 32];

    float4 o0, o1;
    o0.x = tfv(gg0.x * d0.x * r + bb0.x); o0.y = tfv(gg0.y * d0.y * r + bb0.y);
    o0.z = tfv(gg0.z * d0.z * r + bb0.z); o0.w = tfv(gg0.w * d0.w * r + bb0.w);
    o1.x = tfv(gg1.x * d1.x * r + bb1.x); o1.y = tfv(gg1.y * d1.y * r + bb1.y);
    o1.z = tfv(gg1.z * d1.z * r + bb1.z); o1.w = tfv(gg1.w * d1.w * r + bb1.w);

    float4* yr = (float4*)(y + (size_t)row * 256);
    yr[lane] = o0;
    yr[lane + 32] = o1;
}

// ---------------------------------------------------------------------------
// Tensor-core flash attention (unchanged).
// ---------------------------------------------------------------------------
__global__ __launch_bounds__(256, 2) void attn_tc(
    const float* __restrict__ Q, const float* __restrict__ K,
    const float* __restrict__ V, const float* __restrict__ mask,
    float* __restrict__ O)
{
    extern __shared__ unsigned smu[];
    unsigned* Ks = smu;                        // [128][44]
    unsigned* Vs = smu + 128 * 44;             // [128][40]
    unsigned* Ps = smu + 128 * 44 + 128 * 40;  // [128][132]

    const int qt = blockIdx.x;
    const int bh = blockIdx.y;
    const int b = bh >> 3, h = bh & 7;
    const int tid = threadIdx.x;
    const int w = tid >> 5, lane = tid & 31;
    const int gid = lane >> 2, tg = lane & 3;

    const int r0 = w * 16 + gid;
    const int r1 = r0 + 8;
    const size_t qbase = ((size_t)(b * 512 + qt * 128)) * 256 + h * 32;
    const float scale = 0.17677669529663689f;

    unsigned aQ[4][4];
#pragma unroll
    for (int ks = 0; ks < 4; ks++) {
        aQ[ks][0] = f2tf(Q[qbase + (size_t)r0 * 256 + ks * 8 + tg] * scale);
        aQ[ks][1] = f2tf(Q[qbase + (size_t)r1 * 256 + ks * 8 + tg] * scale);
        aQ[ks][2] = f2tf(Q[qbase + (size_t)r0 * 256 + ks * 8 + tg + 4] * scale);
        aQ[ks][3] = f2tf(Q[qbase + (size_t)r1 * 256 + ks * 8 + tg + 4] * scale);
    }
    const bool mz0 = (mask[b * 512 + qt * 128 + r0] == 0.f);
    const bool mz1 = (mask[b * 512 + qt * 128 + r1] == 0.f);

    float m0 = -1e30f, m1 = -1e30f, l0 = 0.f, l1 = 0.f;
    float o[4][4];
#pragma unroll
    for (int nt = 0; nt < 4; nt++)
#pragma unroll
        for (int i = 0; i < 4; i++) o[nt][i] = 0.f;

    for (int kc = 0; kc < 4; kc++) {
        __syncthreads();
        const size_t kvbase = ((size_t)(b * 512 + kc * 128)) * 256 + h * 32;
        for (int idx = tid; idx < 1024; idx += 256) {
            int key = idx >> 3, d4 = idx & 7;
            const uint4* ks4 = (const uint4*)(K + kvbase + (size_t)key * 256) + d4;
            const uint4* vs4 = (const uint4*)(V + kvbase + (size_t)key * 256) + d4;
            *(uint4*)(Ks + key * 44 + d4 * 4) = *ks4;
            *(uint4*)(Vs + key * 40 + d4 * 4) = *vs4;
        }
        __syncthreads();

        float s[16][4];
#pragma unroll
        for (int nt = 0; nt < 16; nt++) {
            s[nt][0] = s[nt][1] = s[nt][2] = s[nt][3] = 0.f;
            const unsigned* kp = Ks + (nt * 8 + gid) * 44;
#pragma unroll
            for (int ks = 0; ks < 4; ks++) {
                unsigned bk[2] = { kp[ks * 8 + tg], kp[ks * 8 + tg + 4] };
                mma_tf32(s[nt], aQ[ks], bk);
            }
        }
        if (mz0) {
#pragma unroll
            for (int nt = 0; nt < 16; nt++) { s[nt][0] = -1e9f; s[nt][1] = -1e9f; }
        }
        if (mz1) {
#pragma unroll
            for (int nt = 0; nt < 16; nt++) { s[nt][2] = -1e9f; s[nt][3] = -1e9f; }
        }

        float rm0 = -1e30f, rm1 = -1e30f;
#pragma unroll
        for (int nt = 0; nt < 16; nt++) {
            rm0 = fmaxf(rm0, fmaxf(s[nt][0], s[nt][1]));
            rm1 = fmaxf(rm1, fmaxf(s[nt][2], s[nt][3]));
        }
        rm0 = fmaxf(rm0, __shfl_xor_sync(0xffffffffu, rm0, 1));
        rm0 = fmaxf(rm0, __shfl_xor_sync(0xffffffffu, rm0, 2));
        rm1 = fmaxf(rm1, __shfl_xor_sync(0xffffffffu, rm1, 1));
        rm1 = fmaxf(rm1, __shfl_xor_sync(0xffffffffu, rm1, 2));
        float mn0 = fmaxf(m0, rm0), mn1 = fmaxf(m1, rm1);
        float c0 = __expf(m0 - mn0), c1 = __expf(m1 - mn1);
        m0 = mn0; m1 = mn1;

        float ps0 = 0.f, ps1 = 0.f;
        unsigned* pr0 = Ps + r0 * 132;
        unsigned* pr1 = Ps + r1 * 132;
#pragma unroll
        for (int nt = 0; nt < 16; nt++) {
            float p00 = __expf(s[nt][0] - mn0), p01 = __expf(s[nt][1] - mn0);
            float p10 = __expf(s[nt][2] - mn1), p11 = __expf(s[nt][3] - mn1);
            ps0 += p00 + p01;
            ps1 += p10 + p11;
            int cc = nt * 8 + 2 * tg;
            pr0[cc] = f2tf(p00); pr0[cc + 1] = f2tf(p01);
            pr1[cc] = f2tf(p10); pr1[cc + 1] = f2tf(p11);
        }
        ps0 += __shfl_xor_sync(0xffffffffu, ps0, 1);
        ps0 += __shfl_xor_sync(0xffffffffu, ps0, 2);
        ps1 += __shfl_xor_sync(0xffffffffu, ps1, 1);
        ps1 += __shfl_xor_sync(0xffffffffu, ps1, 2);
        l0 = l0 * c0 + ps0;
        l1 = l1 * c1 + ps1;
#pragma unroll
        for (int nt = 0; nt < 4; nt++) {
            o[nt][0] *= c0; o[nt][1] *= c0;
            o[nt][2] *= c1; o[nt][3] *= c1;
        }
        __syncwarp();

#pragma unroll
        for (int ks = 0; ks < 16; ks++) {
            unsigned aP[4] = { pr0[ks * 8 + tg], pr1[ks * 8 + tg],
                               pr0[ks * 8 + tg + 4], pr1[ks * 8 + tg + 4] };
#pragma unroll
            for (int nt = 0; nt < 4; nt++) {
                const unsigned* vp = Vs + nt * 8 + gid;
                unsigned bv[2] = { vp[(ks * 8 + tg) * 40], vp[(ks * 8 + tg + 4) * 40] };
                mma_tf32(o[nt], aP, bv);
            }
        }
    }

    float inv0 = 1.f / l0, inv1 = 1.f / l1;
    float* Or0 = O + qbase + (size_t)r0 * 256;
    float* Or1 = O + qbase + (size_t)r1 * 256;
#pragma unroll
    for (int nt = 0; nt < 4; nt++) {
        int cc = nt * 8 + 2 * tg;
        Or0[cc]     = tfv(o[nt][0] * inv0);
        Or0[cc + 1] = tfv(o[nt][1] * inv0);
        Or1[cc]     = tfv(o[nt][2] * inv1);
        Or1[cc + 1] = tfv(o[nt][3] * inv1);
    }
}

// ---------------------------------------------------------------------------
// Weight/input pre-conversion to tf32-rounded fp32 values (unchanged)
// ---------------------------------------------------------------------------
__global__ __launch_bounds__(256) void cvtw_k(
    const float* __restrict__ inputs, const float* __restrict__ emb,
    const float* __restrict__ qkvo, const float* __restrict__ f1,
    const float* __restrict__ f2, float* __restrict__ inT,
    float* __restrict__ wtf)
{
    int idx = blockIdx.x * 256 + threadIdx.x;
    if (idx < 4915200) inT[idx] = tfv(inputs[idx]);
    if (idx < 2042880) {
        float v;
        if (idx < OFF_QKVO)      v = emb[idx - OFF_EMB];
        else if (idx < OFF_FF1)  v = qkvo[idx - OFF_QKVO];
        else if (idx < OFF_FF2)  v = f1[idx - OFF_FF1];
        else                     v = f2[idx - OFF_FF2];
        wtf[idx] = tfv(v);
    }
}

// ---------------------------------------------------------------------------
// LSTM prep: WmR layout [j(8)][lc(128)][k(256)],
//   lc = el*4 + g,  col = g*256 + j*32 + el
// ---------------------------------------------------------------------------
__global__ __launch_bounds__(256) void lstm_prep_k(
    const float* __restrict__ wih, const float* __restrict__ whh,
    const float* __restrict__ bih, const float* __restrict__ bhh,
    const float* __restrict__ dec_h0, const float* __restrict__ out_w1,
    float* __restrict__ WihEncT, float* __restrict__ WmR,
    float* __restrict__ w1t, float* __restrict__ g0,
    float* __restrict__ biasTot, unsigned* __restrict__ syncArr)
{
    int idx = blockIdx.x * 256 + threadIdx.x;
    if (idx < 16) syncArr[idx * 64] = 0u;
    if (idx < 262144) {
        int k = idx >> 10, n = idx & 1023;
        WihEncT[idx] = tfv(wih[(size_t)n * 512 + 256 + k]);

        int j = idx >> 15;           // 0..7
        int r = idx & 32767;
        int lc = r >> 8;             // 0..127
        int kk = r & 255;
        int el = lc >> 2, g = lc & 3;
        int col = g * 256 + j * 32 + el;
        WmR[idx] = wih[(size_t)col * 512 + kk] + whh[(size_t)col * 256 + kk];
    }
    if (idx < 32768) {
        int h = idx >> 8, k = idx & 255;
        w1t[idx] = out_w1[(size_t)k * 128 + h];
    }
    if (idx < 1024) {
        float a = 0.f;
        for (int k = 0; k < 256; k++) a = fmaf(dec_h0[k], whh[(size_t)idx * 256 + k], a);
        g0[idx] = a;
        biasTot[idx] = bih[idx] + bhh[idx];
    }
}

// ---------------------------------------------------------------------------
// Persistent LSTM: 16 INDEPENDENT groups (batches are decoupled!).
// Group m (batches 2m, 2m+1): 8 gate blocks (j = bid&7; each owns e in
// [32j,32j+32), weights 128x256 in smem) + 1 MLP block. Group-local barrier
// (9 arrivals on counter m) — no global coupling.
// ---------------------------------------------------------------------------
__device__ __forceinline__ float sigf(float x) { return 1.f / (1.f + __expf(-x)); }

__device__ __forceinline__ void group_bar(unsigned* syncArr, int m, unsigned target) {
    __threadfence();
    __syncthreads();
    if (threadIdx.x == 0) {
        unsigned* ctr = syncArr + m * 64;
        atomicAdd(ctr, 1u);
        while (*(volatile unsigned*)ctr < target) { }
        __threadfence();
    }
    __syncthreads();
}

__global__ __launch_bounds__(256, 1) void lstm_persist_k(
    const float* __restrict__ pre, const float* __restrict__ WmR,
    const float* __restrict__ w1t, const float* __restrict__ g0,
    const float* __restrict__ dec_c0,
    const float* __restrict__ b1, const float* __restrict__ w2,
    const float* __restrict__ b2, const float* __restrict__ mask,
    float* __restrict__ hbuf, unsigned* __restrict__ syncArr,
    float* __restrict__ out)
{
    extern __shared__ float sm[];
    const int tid = threadIdx.x;

    if (blockIdx.x < 128) {
        // -------- gate block: group m, weight slice j --------
        const int m = blockIdx.x >> 3;
        const int j = blockIdx.x & 7;
        const int b = tid & 1;           // batch within pair
        const int lc = tid >> 1;         // 0..127 = el*4 + g
        const int g = lc & 3;
        const int el = lc >> 2;
        const int e = j * 32 + el;
        const int col = g * 256 + e;
        const int batch = m * 2 + b;
        const int lane = tid & 31;
        const int base = lane & ~6;      // lane of g==0 in this (el',b) group

        float* ws = sm;                  // [128][260] floats
        float* hs = sm + 33280;          // [2][260] floats

        // stage weight slice once (128KB)
        for (int i = tid; i < 32768; i += 256) {
            int r = i >> 8, kk = i & 255;
            ws[r * 260 + kk] = WmR[(size_t)j * 32768 + i];
        }
        const float4* wp = (const float4*)(ws + lc * 260);

        float c = (g == 0) ? dec_c0[e] : 0.f;

        for (int t = 0; t < 512; ++t) {
            float gate;
            if (t == 0) {
                gate = pre[(size_t)batch * 524288 + col] + g0[col];
            } else {
                float prv = __ldg(pre + ((size_t)batch * 512 + t) * 1024 + col);

                // stage h for both batches (2x256 floats)
                for (int i = tid; i < 512; i += 256) {
                    int bb = i >> 8, k = i & 255;
                    hs[bb * 260 + k] =
                        __ldcg(hbuf + (t & 1) * 8192 + (m * 2 + bb) * 256 + k);
                }
                __syncthreads();

                const float4* hp = (const float4*)(hs + b * 260);
                float a0 = 0.f, a1 = 0.f, a2 = 0.f, a3 = 0.f;
#pragma unroll 8
                for (int kk = 0; kk < 64; kk += 4) {
                    float4 h0 = hp[kk],     w0 = wp[kk];
                    float4 h1 = hp[kk + 1], w1v = wp[kk + 1];
                    float4 h2 = hp[kk + 2], w2v = wp[kk + 2];
                    float4 h3 = hp[kk + 3], w3v = wp[kk + 3];
                    a0 = fmaf(h0.x, w0.x, fmaf(h0.y, w0.y, fmaf(h0.z, w0.z, fmaf(h0.w, w0.w, a0))));
                    a1 = fmaf(h1.x, w1v.x, fmaf(h1.y, w1v.y, fmaf(h1.z, w1v.z, fmaf(h1.w, w1v.w, a1))));
                    a2 = fmaf(h2.x, w2v.x, fmaf(h2.y, w2v.y, fmaf(h2.z, w2v.z, fmaf(h2.w, w2v.w, a2))));
                    a3 = fmaf(h3.x, w3v.x, fmaf(h3.y, w3v.y, fmaf(h3.z, w3v.z, fmaf(h3.w, w3v.w, a3))));
                }
                gate = (a0 + a1) + (a2 + a3) + prv;
                __syncthreads();   // dot reads done before next staging
            }

            // gather 4 gates: lanes base+0/2/4/6 hold g=0..3 for this (el', b)
            float gi = __shfl_sync(0xffffffffu, gate, base + 0);
            float gf = __shfl_sync(0xffffffffu, gate, base + 2);
            float gg = __shfl_sync(0xffffffffu, gate, base + 4);
            float go = __shfl_sync(0xffffffffu, gate, base + 6);
            if (g == 0) {
                float cn = sigf(gf) * c + sigf(gi) * tanhf(gg);
                float hn = sigf(go) * tanhf(cn);
                c = cn;
                __stcg(hbuf + ((t + 1) & 1) * 8192 + batch * 256 + e, hn);
            }
            group_bar(syncArr, m, (unsigned)(t + 1) * 9u);
        }
    } else {
        // -------- MLP block: group m, 2 batches, lagged output head --------
        const int m = blockIdx.x - 128;
        const int bat = tid >> 7;
        const int ho = tid & 127;
        float* w1s  = sm;                // [128][260] floats
        float* hrow = sm + 33280;        // [2][256]
        float* red  = sm + 33792;        // [8]

        for (int i = tid; i < 8192; i += 256) {
            int h = i >> 6, k4 = i & 63;
            ((float4*)w1s)[h * 65 + k4] = ((const float4*)w1t)[i];
        }
        float w2v = w2[ho];
        float b1v = b1[ho];
        float b2v = b2[0];

        for (int t = 0; t <= 512; ++t) {
            if (t >= 1) {
                for (int i = tid; i < 512; i += 256) {
                    int bb = i >> 8, k = i & 255;
                    hrow[bb * 256 + k] =
                        __ldcg(hbuf + (t & 1) * 8192 + (m * 2 + bb) * 256 + k);
                }
                __syncthreads();

                float a = b1v;
                const float4* h4 = (const float4*)(hrow + bat * 256);
                const float4* w4 = (const float4*)(w1s + ho * 260);
#pragma unroll 16
                for (int kk = 0; kk < 64; kk++) {
                    float4 hv = h4[kk];
                    float4 wv = w4[kk];
                    a = fmaf(hv.x, wv.x, fmaf(hv.y, wv.y, fmaf(hv.z, wv.z, fmaf(hv.w, wv.w, a))));
                }
                float contrib = fmaxf(a, 0.f) * w2v;
#pragma unroll
                for (int o = 16; o > 0; o >>= 1)
                    contrib += __shfl_down_sync(0xffffffffu, contrib, o);
                if ((tid & 31) == 0) red[tid >> 5] = contrib;
                __syncthreads();
                if (tid == 0) {
                    int bidx = m * 2;
                    float pp = red[0] + red[1] + red[2] + red[3] + b2v;
                    out[bidx * 512 + (t - 1)] = pp * mask[bidx * 512 + (t - 1)];
                }
                if (tid == 128) {
                    int bidx = m * 2 + 1;
                    float pp = red[4] + red[5] + red[6] + red[7] + b2v;
                    out[bidx * 512 + (t - 1)] = pp * mask[bidx * 512 + (t - 1)];
                }
                __syncthreads();
            }
            if (t < 512) group_bar(syncArr, m, (unsigned)(t + 1) * 9u);
        }
    }
}

// ---------------------------------------------------------------------------
// Launcher
// ---------------------------------------------------------------------------
extern "C" void kernel_launch(void* const* d_in, const int* in_sizes, int n_in,
                              void* d_out, int out_size)
{
    const float* inputs   = (const float*)d_in[0];
    const float* mask     = (const float*)d_in[1];
    /* d_in[2] = lengths (unused) */
    const float* embed_w  = (const float*)d_in[3];
    const float* embed_b  = (const float*)d_in[4];
    const float* qkvo_w   = (const float*)d_in[5];
    const float* qkvo_b   = (const float*)d_in[6];
    const float* ln_g     = (const float*)d_in[7];
    const float* ln_b     = (const float*)d_in[8];
    const float* ff_w1    = (const float*)d_in[9];
    const float* ff_b1    = (const float*)d_in[10];
    const float* ff_w2    = (const float*)d_in[11];
    const float* ff_b2    = (const float*)d_in[12];
    const float* enc_ln_g = (const float*)d_in[13];
    const float* enc_ln_b = (const float*)d_in[14];
    const float* wih      = (const float*)d_in[15];
    const float* whh      = (const float*)d_in[16];
    const float* bih      = (const float*)d_in[17];
    const float* bhh      = (const float*)d_in[18];
    const float* dec_h0   = (const float*)d_in[19];
    const float* dec_c0   = (const float*)d_in[20];
    const float* out_w1   = (const float*)d_in[21];
    const float* out_b1   = (const float*)d_in[22];
    const float* out_w2   = (const float*)d_in[23];
    const float* out_b2   = (const float*)d_in[24];
    float* out = (float*)d_out;
    (void)in_sizes; (void)n_in; (void)out_size;

    float *px, *py, *pqkv, *po, *ph1, *ppre, *pinT, *pwtf, *pWET, *pWmR, *pw1t,
          *pg0, *pbt, *phb;
    unsigned* psync;
    cudaGetSymbolAddress((void**)&px,    g_x);
    cudaGetSymbolAddress((void**)&py,    g_y);
    cudaGetSymbolAddress((void**)&pqkv,  g_qkv);
    cudaGetSymbolAddress((void**)&po,    g_o);
    cudaGetSymbolAddress((void**)&ph1,   g_h1);
    cudaGetSymbolAddress((void**)&ppre,  g_pre);
    cudaGetSymbolAddress((void**)&pinT,  g_inT);
    cudaGetSymbolAddress((void**)&pwtf,  g_wtf);
    cudaGetSymbolAddress((void**)&pWET,  g_WihEncT);
    cudaGetSymbolAddress((void**)&pWmR,  g_WmR);
    cudaGetSymbolAddress((void**)&pw1t,  g_w1t);
    cudaGetSymbolAddress((void**)&pg0,   g_g0);
    cudaGetSymbolAddress((void**)&pbt,   g_biasTot);
    cudaGetSymbolAddress((void**)&phb,   g_hbuf);
    cudaGetSymbolAddress((void**)&psync, g_syncArr);

    cudaFuncSetAttribute(gemm_tc, cudaFuncAttributeMaxDynamicSharedMemorySize, GEMM_SMEM);
    cudaFuncSetAttribute(attn_tc, cudaFuncAttributeMaxDynamicSharedMemorySize, 110592);
    cudaFuncSetAttribute(lstm_persist_k, cudaFuncAttributeMaxDynamicSharedMemorySize, 137216);

    const int M = 16384;
    const long QKV_C = 16384L * 256;

    // prep: tf32 conversions + LSTM weights + barrier reset
    cvtw_k<<<19200, 256>>>(inputs, embed_w, qkvo_w, ff_w1, ff_w2, pinT, pwtf);
    lstm_prep_k<<<1024, 256>>>(wih, whh, bih, bhh, dec_h0, out_w1,
                               pWET, pWmR, pw1t, pg0, pbt, psync);

    // Embed (K=300)
    gemm_tc<<<dim3(2, 128), 256, GEMM_SMEM>>>(pinT, pwtf + OFF_EMB, embed_b,
                                              nullptr, px,
                                              M, 256, 300, 0, 0, 2, 0, 0, 0);

    // Transformer layers
    for (int l = 0; l < 6; l++) {
        const float* Wq = pwtf + OFF_QKVO + (size_t)(l * 4) * 65536;
        const float* Wo = pwtf + OFF_QKVO + (size_t)(l * 4 + 3) * 65536;
        const float* bq = qkvo_b + (l * 4) * 256;
        const float* bo = qkvo_b + (l * 4 + 3) * 256;

        layernorm_k<<<2048, 256>>>(px, ln_g + l * 512, ln_b + l * 512, py);
        gemm_tc<<<dim3(6, 128), 256, GEMM_SMEM>>>(py, Wq, bq, nullptr, pqkv,
                                                  M, 256, 256, 0, 1,
                                                  2, 65536, QKV_C, 256);
        attn_tc<<<dim3(4, 256), 256, 110592>>>(pqkv, pqkv + QKV_C,
                                               pqkv + 2 * QKV_C, mask, po);
        gemm_tc<<<dim3(2, 128), 256, GEMM_SMEM>>>(po, Wo, bo, px, px,
                                                  M, 256, 256, 0, 0, 2, 0, 0, 0);

        layernorm_k<<<2048, 256>>>(px, ln_g + l * 512 + 256, ln_b + l * 512 + 256, py);
        gemm_tc<<<dim3(1, 128), 256, GEMM_SMEM>>>(py, pwtf + OFF_FF1 + (size_t)l * 32768,
                                                  ff_b1 + l * 128, nullptr, ph1,
                                                  M, 128, 256, 1, 1, 1, 0, 0, 0);
        gemm_tc<<<dim3(2, 128), 256, GEMM_SMEM>>>(ph1, pwtf + OFF_FF2 + (size_t)l * 32768,
                                                  ff_b2 + l * 256, px, px,
                                                  M, 256, 128, 0, 0, 2, 0, 0, 0);
    }

    // Encoder LN -> enc (in py, tf32-rounded)
    layernorm_k<<<2048, 256>>>(px, enc_ln_g, enc_ln_b, py);

    // pre = enc @ wih[:,256:].T + (bih+bhh)
    gemm_tc<<<dim3(8, 128), 256, GEMM_SMEM>>>(py, pWET, pbt, nullptr, ppre,
                                              M, 1024, 256, 0, 0, 8, 0, 0, 0);

    // Persistent LSTM scan + output head (144 blocks, 16 independent groups)
    lstm_persist_k<<<144, 256, 137216>>>(ppre, pWmR, pw1t, pg0, dec_c0,
                                         out_b1, out_w2, out_b2, mask,
                                         phb, psync, out);
}

// round 13
// speedup vs baseline: 1.1948x; 1.0226x over previous
#include <cuda_runtime.h>
#include <cuda_bf16.h>
#include <math.h>

// ---------------------------------------------------------------------------
// Scratch (device globals — allocation-free per harness rules)
// ---------------------------------------------------------------------------
__device__ float g_x   [16384 * 256];
__device__ float g_y   [16384 * 256];
__device__ float g_qkv [3 * 16384 * 256];
__device__ float g_o   [16384 * 256];
__device__ float g_h1  [16384 * 128];
__device__ float g_pre [16384 * 1024];
__device__ float g_inT [16384 * 300];     // tf32-rounded inputs
__device__ float g_wtf [2042880];         // tf32-rounded weights (emb|qkvo|ff1|ff2)
__device__ float g_WihEncT[256 * 1024];   // (wih[:,256:512]).T, tf32-rounded
__device__ float g_WmR [8 * 128 * 256];   // merged (wih+whh).T, [j][lc][k]
__device__ float g_w1t [128 * 256];       // out_w1 transposed [h][k]
__device__ float g_g0  [1024];            // dec_h0 @ whh.T
__device__ float g_biasTot[1024];         // bih + bhh
__device__ float g_hbuf[2 * 32 * 256];
__device__ unsigned g_syncArr[16 * 64];   // 16 group counters, 256B apart

#define OFF_EMB  0
#define OFF_QKVO 76800
#define OFF_FF1  1649664
#define OFF_FF2  1846272

// ---------------------------------------------------------------------------
// tf32 / mma helpers
// ---------------------------------------------------------------------------
__device__ __forceinline__ unsigned f2tf(float f) {
    unsigned u;
    asm("cvt.rna.tf32.f32 %0, %1;" : "=r"(u) : "f"(f));
    return u;
}
__device__ __forceinline__ float tfv(float f) { return __uint_as_float(f2tf(f)); }

__device__ __forceinline__ void mma_tf32(float (&d)[4], const unsigned (&a)[4],
                                         const unsigned (&b)[2]) {
    asm volatile(
        "mma.sync.aligned.m16n8k8.row.col.f32.tf32.tf32.f32 "
        "{%0,%1,%2,%3}, {%4,%5,%6,%7}, {%8,%9}, {%0,%1,%2,%3};"
        : "+f"(d[0]), "+f"(d[1]), "+f"(d[2]), "+f"(d[3])
        : "r"(a[0]), "r"(a[1]), "r"(a[2]), "r"(a[3]), "r"(b[0]), "r"(b[1]));
}

__device__ __forceinline__ void cp16(unsigned dst, const void* src, int bytes) {
    asm volatile("cp.async.cg.shared.global [%0], [%1], 16, %2;"
                 :: "r"(dst), "l"(src), "r"(bytes));
}
__device__ __forceinline__ void cp_commit() {
    asm volatile("cp.async.commit_group;" ::: "memory");
}

// ---------------------------------------------------------------------------
// tf32 tensor-core GEMM (unchanged / passing).
// ---------------------------------------------------------------------------
#define GEMM_SMEM (3 * 128 * 20 * 4 + 3 * 16 * 136 * 4)

__global__ __launch_bounds__(256, 2) void gemm_tc(
    const float* __restrict__ A, const float* __restrict__ B,
    const float* __restrict__ bias, const float* __restrict__ res,
    float* __restrict__ C, int M, int N, int K, int relu, int outCvt,
    int nxPerMat, long bMatStride, long cMatStride, int biasMatStride)
{
    extern __shared__ unsigned dynsm[];
    unsigned (*As)[128][20] = (unsigned (*)[128][20])dynsm;
    unsigned (*Bs)[16][136] = (unsigned (*)[16][136])(dynsm + 3 * 128 * 20);

    const int tid = threadIdx.x;
    const int bx = blockIdx.x, by = blockIdx.y;
    const int mat = bx / nxPerMat;
    const int bxn = bx - mat * nxPerMat;

    const float* Bp    = B + (size_t)mat * bMatStride;
    const float* biasP = bias + (size_t)mat * biasMatStride;
    float*       Cp    = C + (size_t)mat * cMatStride;

    const float* Ablk = A + (size_t)(by * 128) * K;
    const float* Bblk = Bp + bxn * 128;

    const int lane = tid & 31, wid = tid >> 5;
    const int wm = wid >> 2, wn = wid & 3;
    const int gid = lane >> 2, tg = lane & 3;

    const int ar0 = tid >> 2, ac0 = (tid & 3) << 2;
    const int ar1 = ar0 + 64;
    const int bk0 = tid >> 5, bc0 = (tid & 31) << 2;
    const int bk1 = bk0 + 8;

    const unsigned sA = (unsigned)__cvta_generic_to_shared(&dynsm[0]);
    const unsigned sB = (unsigned)__cvta_generic_to_shared(&dynsm[3 * 128 * 20]);

    float acc[4][4][4];
#pragma unroll
    for (int mt = 0; mt < 4; mt++)
#pragma unroll
        for (int nt = 0; nt < 4; nt++)
#pragma unroll
            for (int i = 0; i < 4; i++) acc[mt][nt][i] = 0.f;

    auto issue = [&](int buf, int k0) {
        int c0 = k0 + ac0;
        int rem0 = K - c0;
        int by0 = rem0 >= 4 ? 16 : (rem0 > 0 ? rem0 * 4 : 0);
        cp16(sA + ((buf * 128 + ar0) * 20 + ac0) * 4,
             Ablk + (size_t)ar0 * K + (by0 ? c0 : 0), by0);
        cp16(sA + ((buf * 128 + ar1) * 20 + ac0) * 4,
             Ablk + (size_t)ar1 * K + (by0 ? c0 : 0), by0);
        int kr0 = k0 + bk0;
        int bb0 = (kr0 < K) ? 16 : 0;
        cp16(sB + ((buf * 16 + bk0) * 136 + bc0) * 4,
             Bblk + (size_t)(bb0 ? kr0 : 0) * N + bc0, bb0);
        int kr1 = k0 + bk1;
        int bb1 = (kr1 < K) ? 16 : 0;
        cp16(sB + ((buf * 16 + bk1) * 136 + bc0) * 4,
             Bblk + (size_t)(bb1 ? kr1 : 0) * N + bc0, bb1);
        cp_commit();
    };

    issue(0, 0);
    if (16 < K) issue(1, 16);

    int cur = 0;
    for (int k0 = 0; k0 < K; k0 += 16) {
        if (k0 + 16 < K) {
            asm volatile("cp.async.wait_group 1;" ::: "memory");
        } else {
            asm volatile("cp.async.wait_group 0;" ::: "memory");
        }
        __syncthreads();
        if (k0 + 32 < K) {
            int nb = cur + 2; if (nb >= 3) nb -= 3;
            issue(nb, k0 + 32);
        }

#pragma unroll
        for (int ks = 0; ks < 16; ks += 8) {
            unsigned a[4][4], b[4][2];
#pragma unroll
            for (int mt = 0; mt < 4; mt++) {
                int r = wm * 64 + mt * 16 + gid;
                a[mt][0] = As[cur][r][ks + tg];
                a[mt][1] = As[cur][r + 8][ks + tg];
                a[mt][2] = As[cur][r][ks + tg + 4];
                a[mt][3] = As[cur][r + 8][ks + tg + 4];
            }
#pragma unroll
            for (int nt = 0; nt < 4; nt++) {
                int cb = wn * 32 + nt * 8 + gid;
                b[nt][0] = Bs[cur][ks + tg][cb];
                b[nt][1] = Bs[cur][ks + tg + 4][cb];
            }
#pragma unroll
            for (int mt = 0; mt < 4; mt++)
#pragma unroll
                for (int nt = 0; nt < 4; nt++)
                    mma_tf32(acc[mt][nt], a[mt], b[nt]);
        }
        __syncthreads();
        cur = cur + 1; if (cur >= 3) cur -= 3;
    }

#pragma unroll
    for (int mt = 0; mt < 4; mt++) {
        int r0 = by * 128 + wm * 64 + mt * 16 + gid;
#pragma unroll
        for (int nt = 0; nt < 4; nt++) {
            int c0 = bxn * 128 + wn * 32 + nt * 8 + tg * 2;
            float bza = biasP[c0], bzb = biasP[c0 + 1];
            size_t off0 = (size_t)r0 * N + c0;
            size_t off1 = (size_t)(r0 + 8) * N + c0;
            float v0 = acc[mt][nt][0] + bza, v1 = acc[mt][nt][1] + bzb;
            float v2 = acc[mt][nt][2] + bza, v3 = acc[mt][nt][3] + bzb;
            if (res) {
                v0 += res[off0]; v1 += res[off0 + 1];
                v2 += res[off1]; v3 += res[off1 + 1];
            }
            if (relu) {
                v0 = fmaxf(v0, 0.f); v1 = fmaxf(v1, 0.f);
                v2 = fmaxf(v2, 0.f); v3 = fmaxf(v3, 0.f);
            }
            if (outCvt) {
                v0 = tfv(v0); v1 = tfv(v1); v2 = tfv(v2); v3 = tfv(v3);
            }
            *(float2*)(Cp + off0) = make_float2(v0, v1);
            *(float2*)(Cp + off1) = make_float2(v2, v3);
        }
    }
}

// ---------------------------------------------------------------------------
// LayerNorm (unchanged).
// ---------------------------------------------------------------------------
__global__ __launch_bounds__(256) void layernorm_k(
    const float* __restrict__ x, const float* __restrict__ g,
    const float* __restrict__ b, float* __restrict__ y)
{
    int tid = threadIdx.x;
    int lane = tid & 31;
    int row = blockIdx.x * 8 + (tid >> 5);

    const float4* xr = (const float4*)(x + (size_t)row * 256);
    float4 v0 = xr[lane], v1 = xr[lane + 32];

    float s = v0.x + v0.y + v0.z + v0.w + v1.x + v1.y + v1.z + v1.w;
#pragma unroll
    for (int o = 16; o > 0; o >>= 1) s += __shfl_xor_sync(0xffffffffu, s, o);
    float mean = s * (1.f / 256.f);

    float4 d0 = make_float4(v0.x - mean, v0.y - mean, v0.z - mean, v0.w - mean);
    float4 d1 = make_float4(v1.x - mean, v1.y - mean, v1.z - mean, v1.w - mean);
    float sq = d0.x * d0.x + d0.y * d0.y + d0.z * d0.z + d0.w * d0.w
             + d1.x * d1.x + d1.y * d1.y + d1.z * d1.z + d1.w * d1.w;
#pragma unroll
    for (int o = 16; o > 0; o >>= 1) sq += __shfl_xor_sync(0xffffffffu, sq, o);
    float var = sq * (1.f / 255.f);
    float r = 1.f / (sqrtf(var) + 1e-6f);

    const float4* g4 = (const float4*)g;
    const float4* b4 = (const float4*)b;
    float4 gg0 = g4[lane], gg1 = g4[lane + 32];
    float4 bb0 = b4[lane], bb1 = b4[lane + 32];

    float4 o0, o1;
    o0.x = tfv(gg0.x * d0.x * r + bb0.x); o0.y = tfv(gg0.y * d0.y * r + bb0.y);
    o0.z = tfv(gg0.z * d0.z * r + bb0.z); o0.w = tfv(gg0.w * d0.w * r + bb0.w);
    o1.x = tfv(gg1.x * d1.x * r + bb1.x); o1.y = tfv(gg1.y * d1.y * r + bb1.y);
    o1.z = tfv(gg1.z * d1.z * r + bb1.z); o1.w = tfv(gg1.w * d1.w * r + bb1.w);

    float4* yr = (float4*)(y + (size_t)row * 256);
    yr[lane] = o0;
    yr[lane + 32] = o1;
}

// ---------------------------------------------------------------------------
// Tensor-core flash attention (unchanged).
// ---------------------------------------------------------------------------
__global__ __launch_bounds__(256, 2) void attn_tc(
    const float* __restrict__ Q, const float* __restrict__ K,
    const float* __restrict__ V, const float* __restrict__ mask,
    float* __restrict__ O)
{
    extern __shared__ unsigned smu[];
    unsigned* Ks = smu;                        // [128][44]
    unsigned* Vs = smu + 128 * 44;             // [128][40]
    unsigned* Ps = smu + 128 * 44 + 128 * 40;  // [128][132]

    const int qt = blockIdx.x;
    const int bh = blockIdx.y;
    const int b = bh >> 3, h = bh & 7;
    const int tid = threadIdx.x;
    const int w = tid >> 5, lane = tid & 31;
    const int gid = lane >> 2, tg = lane & 3;

    const int r0 = w * 16 + gid;
    const int r1 = r0 + 8;
    const size_t qbase = ((size_t)(b * 512 + qt * 128)) * 256 + h * 32;
    const float scale = 0.17677669529663689f;

    unsigned aQ[4][4];
#pragma unroll
    for (int ks = 0; ks < 4; ks++) {
        aQ[ks][0] = f2tf(Q[qbase + (size_t)r0 * 256 + ks * 8 + tg] * scale);
        aQ[ks][1] = f2tf(Q[qbase + (size_t)r1 * 256 + ks * 8 + tg] * scale);
        aQ[ks][2] = f2tf(Q[qbase + (size_t)r0 * 256 + ks * 8 + tg + 4] * scale);
        aQ[ks][3] = f2tf(Q[qbase + (size_t)r1 * 256 + ks * 8 + tg + 4] * scale);
    }
    const bool mz0 = (mask[b * 512 + qt * 128 + r0] == 0.f);
    const bool mz1 = (mask[b * 512 + qt * 128 + r1] == 0.f);

    float m0 = -1e30f, m1 = -1e30f, l0 = 0.f, l1 = 0.f;
    float o[4][4];
#pragma unroll
    for (int nt = 0; nt < 4; nt++)
#pragma unroll
        for (int i = 0; i < 4; i++) o[nt][i] = 0.f;

    for (int kc = 0; kc < 4; kc++) {
        __syncthreads();
        const size_t kvbase = ((size_t)(b * 512 + kc * 128)) * 256 + h * 32;
        for (int idx = tid; idx < 1024; idx += 256) {
            int key = idx >> 3, d4 = idx & 7;
            const uint4* ks4 = (const uint4*)(K + kvbase + (size_t)key * 256) + d4;
            const uint4* vs4 = (const uint4*)(V + kvbase + (size_t)key * 256) + d4;
            *(uint4*)(Ks + key * 44 + d4 * 4) = *ks4;
            *(uint4*)(Vs + key * 40 + d4 * 4) = *vs4;
        }
        __syncthreads();

        float s[16][4];
#pragma unroll
        for (int nt = 0; nt < 16; nt++) {
            s[nt][0] = s[nt][1] = s[nt][2] = s[nt][3] = 0.f;
            const unsigned* kp = Ks + (nt * 8 + gid) * 44;
#pragma unroll
            for (int ks = 0; ks < 4; ks++) {
                unsigned bk[2] = { kp[ks * 8 + tg], kp[ks * 8 + tg + 4] };
                mma_tf32(s[nt], aQ[ks], bk);
            }
        }
        if (mz0) {
#pragma unroll
            for (int nt = 0; nt < 16; nt++) { s[nt][0] = -1e9f; s[nt][1] = -1e9f; }
        }
        if (mz1) {
#pragma unroll
            for (int nt = 0; nt < 16; nt++) { s[nt][2] = -1e9f; s[nt][3] = -1e9f; }
        }

        float rm0 = -1e30f, rm1 = -1e30f;
#pragma unroll
        for (int nt = 0; nt < 16; nt++) {
            rm0 = fmaxf(rm0, fmaxf(s[nt][0], s[nt][1]));
            rm1 = fmaxf(rm1, fmaxf(s[nt][2], s[nt][3]));
        }
        rm0 = fmaxf(rm0, __shfl_xor_sync(0xffffffffu, rm0, 1));
        rm0 = fmaxf(rm0, __shfl_xor_sync(0xffffffffu, rm0, 2));
        rm1 = fmaxf(rm1, __shfl_xor_sync(0xffffffffu, rm1, 1));
        rm1 = fmaxf(rm1, __shfl_xor_sync(0xffffffffu, rm1, 2));
        float mn0 = fmaxf(m0, rm0), mn1 = fmaxf(m1, rm1);
        float c0 = __expf(m0 - mn0), c1 = __expf(m1 - mn1);
        m0 = mn0; m1 = mn1;

        float ps0 = 0.f, ps1 = 0.f;
        unsigned* pr0 = Ps + r0 * 132;
        unsigned* pr1 = Ps + r1 * 132;
#pragma unroll
        for (int nt = 0; nt < 16; nt++) {
            float p00 = __expf(s[nt][0] - mn0), p01 = __expf(s[nt][1] - mn0);
            float p10 = __expf(s[nt][2] - mn1), p11 = __expf(s[nt][3] - mn1);
            ps0 += p00 + p01;
            ps1 += p10 + p11;
            int cc = nt * 8 + 2 * tg;
            pr0[cc] = f2tf(p00); pr0[cc + 1] = f2tf(p01);
            pr1[cc] = f2tf(p10); pr1[cc + 1] = f2tf(p11);
        }
        ps0 += __shfl_xor_sync(0xffffffffu, ps0, 1);
        ps0 += __shfl_xor_sync(0xffffffffu, ps0, 2);
        ps1 += __shfl_xor_sync(0xffffffffu, ps1, 1);
        ps1 += __shfl_xor_sync(0xffffffffu, ps1, 2);
        l0 = l0 * c0 + ps0;
        l1 = l1 * c1 + ps1;
#pragma unroll
        for (int nt = 0; nt < 4; nt++) {
            o[nt][0] *= c0; o[nt][1] *= c0;
            o[nt][2] *= c1; o[nt][3] *= c1;
        }
        __syncwarp();

#pragma unroll
        for (int ks = 0; ks < 16; ks++) {
            unsigned aP[4] = { pr0[ks * 8 + tg], pr1[ks * 8 + tg],
                               pr0[ks * 8 + tg + 4], pr1[ks * 8 + tg + 4] };
#pragma unroll
            for (int nt = 0; nt < 4; nt++) {
                const unsigned* vp = Vs + nt * 8 + gid;
                unsigned bv[2] = { vp[(ks * 8 + tg) * 40], vp[(ks * 8 + tg + 4) * 40] };
                mma_tf32(o[nt], aP, bv);
            }
        }
    }

    float inv0 = 1.f / l0, inv1 = 1.f / l1;
    float* Or0 = O + qbase + (size_t)r0 * 256;
    float* Or1 = O + qbase + (size_t)r1 * 256;
#pragma unroll
    for (int nt = 0; nt < 4; nt++) {
        int cc = nt * 8 + 2 * tg;
        Or0[cc]     = tfv(o[nt][0] * inv0);
        Or0[cc + 1] = tfv(o[nt][1] * inv0);
        Or1[cc]     = tfv(o[nt][2] * inv1);
        Or1[cc + 1] = tfv(o[nt][3] * inv1);
    }
}

// ---------------------------------------------------------------------------
// Weight/input pre-conversion to tf32-rounded fp32 values (unchanged)
// ---------------------------------------------------------------------------
__global__ __launch_bounds__(256) void cvtw_k(
    const float* __restrict__ inputs, const float* __restrict__ emb,
    const float* __restrict__ qkvo, const float* __restrict__ f1,
    const float* __restrict__ f2, float* __restrict__ inT,
    float* __restrict__ wtf)
{
    int idx = blockIdx.x * 256 + threadIdx.x;
    if (idx < 4915200) inT[idx] = tfv(inputs[idx]);
    if (idx < 2042880) {
        float v;
        if (idx < OFF_QKVO)      v = emb[idx - OFF_EMB];
        else if (idx < OFF_FF1)  v = qkvo[idx - OFF_QKVO];
        else if (idx < OFF_FF2)  v = f1[idx - OFF_FF1];
        else                     v = f2[idx - OFF_FF2];
        wtf[idx] = tfv(v);
    }
}

// ---------------------------------------------------------------------------
// LSTM prep (unchanged from R12): WmR [j(8)][lc(128)][k(256)],
//   lc = el*4 + g,  col = g*256 + j*32 + el
// ---------------------------------------------------------------------------
__global__ __launch_bounds__(256) void lstm_prep_k(
    const float* __restrict__ wih, const float* __restrict__ whh,
    const float* __restrict__ bih, const float* __restrict__ bhh,
    const float* __restrict__ dec_h0, const float* __restrict__ out_w1,
    float* __restrict__ WihEncT, float* __restrict__ WmR,
    float* __restrict__ w1t, float* __restrict__ g0,
    float* __restrict__ biasTot, unsigned* __restrict__ syncArr)
{
    int idx = blockIdx.x * 256 + threadIdx.x;
    if (idx < 16) syncArr[idx * 64] = 0u;
    if (idx < 262144) {
        int k = idx >> 10, n = idx & 1023;
        WihEncT[idx] = tfv(wih[(size_t)n * 512 + 256 + k]);

        int j = idx >> 15;           // 0..7
        int r = idx & 32767;
        int lc = r >> 8;             // 0..127
        int kk = r & 255;
        int el = lc >> 2, g = lc & 3;
        int col = g * 256 + j * 32 + el;
        WmR[idx] = wih[(size_t)col * 512 + kk] + whh[(size_t)col * 256 + kk];
    }
    if (idx < 32768) {
        int h = idx >> 8, k = idx & 255;
        w1t[idx] = out_w1[(size_t)k * 128 + h];
    }
    if (idx < 1024) {
        float a = 0.f;
        for (int k = 0; k < 256; k++) a = fmaf(dec_h0[k], whh[(size_t)idx * 256 + k], a);
        g0[idx] = a;
        biasTot[idx] = bih[idx] + bhh[idx];
    }
}

// ---------------------------------------------------------------------------
// Persistent LSTM: 16 independent groups. Single change vs R12: each gate
// thread keeps the first half of its weight row (kk 0..31, 32 float4 = 128
// regs) in REGISTERS (loaded once), and reads only kk 32..63 from smem —
// halves per-step smem traffic (1536 -> 1024 cyc/SM, overlapping FMA floor).
// ---------------------------------------------------------------------------
__device__ __forceinline__ float sigf(float x) { return 1.f / (1.f + __expf(-x)); }

__device__ __forceinline__ void group_bar(unsigned* syncArr, int m, unsigned target) {
    __threadfence();
    __syncthreads();
    if (threadIdx.x == 0) {
        unsigned* ctr = syncArr + m * 64;
        atomicAdd(ctr, 1u);
        while (*(volatile unsigned*)ctr < target) { }
        __threadfence();
    }
    __syncthreads();
}

__global__ __launch_bounds__(256, 1) void lstm_persist_k(
    const float* __restrict__ pre, const float* __restrict__ WmR,
    const float* __restrict__ w1t, const float* __restrict__ g0,
    const float* __restrict__ dec_c0,
    const float* __restrict__ b1, const float* __restrict__ w2,
    const float* __restrict__ b2, const float* __restrict__ mask,
    float* __restrict__ hbuf, unsigned* __restrict__ syncArr,
    float* __restrict__ out)
{
    extern __shared__ float sm[];
    const int tid = threadIdx.x;

    if (blockIdx.x < 128) {
        // -------- gate block: group m, weight slice j --------
        const int m = blockIdx.x >> 3;
        const int j = blockIdx.x & 7;
        const int b = tid & 1;           // batch within pair
        const int lc = tid >> 1;         // 0..127 = el*4 + g
        const int g = lc & 3;
        const int el = lc >> 2;
        const int e = j * 32 + el;
        const int col = g * 256 + e;
        const int batch = m * 2 + b;
        const int lane = tid & 31;
        const int base = lane & ~6;      // lane of g==0 in this (el',b) group

        float* ws = sm;                  // [128][132] floats (kk 32..63 half only)
        float* hs = sm + 16896;          // [2][260] floats

        // register half of the weight row: kk 0..31 (128 floats)
        const float4* wgl = (const float4*)(WmR + (size_t)j * 32768 + (size_t)lc * 256);
        float4 wreg[32];
#pragma unroll
        for (int kk = 0; kk < 32; kk++) wreg[kk] = wgl[kk];

        // stage smem half (kk 32..63 -> 128 floats per row, stride 132)
        for (int i = tid; i < 16384; i += 256) {
            int r = i >> 7, kk = i & 127;
            ws[r * 132 + kk] = WmR[(size_t)j * 32768 + (size_t)r * 256 + 128 + kk];
        }
        const float4* wp = (const float4*)(ws + lc * 132);

        float c = (g == 0) ? dec_c0[e] : 0.f;

        for (int t = 0; t < 512; ++t) {
            float gate;
            if (t == 0) {
                gate = pre[(size_t)batch * 524288 + col] + g0[col];
            } else {
                float prv = __ldg(pre + ((size_t)batch * 512 + t) * 1024 + col);

                // stage h for both batches (2x256 floats)
                for (int i = tid; i < 512; i += 256) {
                    int bb = i >> 8, k = i & 255;
                    hs[bb * 260 + k] =
                        __ldcg(hbuf + (t & 1) * 8192 + (m * 2 + bb) * 256 + k);
                }
                __syncthreads();

                const float4* hp = (const float4*)(hs + b * 260);
                float a0 = 0.f, a1 = 0.f, a2 = 0.f, a3 = 0.f;
                // first half from registers
#pragma unroll 8
                for (int kk = 0; kk < 32; kk += 4) {
                    float4 h0 = hp[kk],     w0 = wreg[kk];
                    float4 h1 = hp[kk + 1], w1v = wreg[kk + 1];
                    float4 h2 = hp[kk + 2], w2v = wreg[kk + 2];
                    float4 h3 = hp[kk + 3], w3v = wreg[kk + 3];
                    a0 = fmaf(h0.x, w0.x, fmaf(h0.y, w0.y, fmaf(h0.z, w0.z, fmaf(h0.w, w0.w, a0))));
                    a1 = fmaf(h1.x, w1v.x, fmaf(h1.y, w1v.y, fmaf(h1.z, w1v.z, fmaf(h1.w, w1v.w, a1))));
                    a2 = fmaf(h2.x, w2v.x, fmaf(h2.y, w2v.y, fmaf(h2.z, w2v.z, fmaf(h2.w, w2v.w, a2))));
                    a3 = fmaf(h3.x, w3v.x, fmaf(h3.y, w3v.y, fmaf(h3.z, w3v.z, fmaf(h3.w, w3v.w, a3))));
                }
                // second half from smem
#pragma unroll 8
                for (int kk = 0; kk < 32; kk += 4) {
                    float4 h0 = hp[32 + kk],     w0 = wp[kk];
                    float4 h1 = hp[32 + kk + 1], w1v = wp[kk + 1];
                    float4 h2 = hp[32 + kk + 2], w2v = wp[kk + 2];
                    float4 h3 = hp[32 + kk + 3], w3v = wp[kk + 3];
                    a0 = fmaf(h0.x, w0.x, fmaf(h0.y, w0.y, fmaf(h0.z, w0.z, fmaf(h0.w, w0.w, a0))));
                    a1 = fmaf(h1.x, w1v.x, fmaf(h1.y, w1v.y, fmaf(h1.z, w1v.z, fmaf(h1.w, w1v.w, a1))));
                    a2 = fmaf(h2.x, w2v.x, fmaf(h2.y, w2v.y, fmaf(h2.z, w2v.z, fmaf(h2.w, w2v.w, a2))));
                    a3 = fmaf(h3.x, w3v.x, fmaf(h3.y, w3v.y, fmaf(h3.z, w3v.z, fmaf(h3.w, w3v.w, a3))));
                }
                gate = (a0 + a1) + (a2 + a3) + prv;
                __syncthreads();   // dot reads done before next staging
            }

            // gather 4 gates: lanes base+0/2/4/6 hold g=0..3 for this (el', b)
            float gi = __shfl_sync(0xffffffffu, gate, base + 0);
            float gf = __shfl_sync(0xffffffffu, gate, base + 2);
            float gg = __shfl_sync(0xffffffffu, gate, base + 4);
            float go = __shfl_sync(0xffffffffu, gate, base + 6);
            if (g == 0) {
                float cn = sigf(gf) * c + sigf(gi) * tanhf(gg);
                float hn = sigf(go) * tanhf(cn);
                c = cn;
                __stcg(hbuf + ((t + 1) & 1) * 8192 + batch * 256 + e, hn);
            }
            group_bar(syncArr, m, (unsigned)(t + 1) * 9u);
        }
    } else {
        // -------- MLP block: group m, 2 batches, lagged output head --------
        const int m = blockIdx.x - 128;
        const int bat = tid >> 7;
        const int ho = tid & 127;
        float* w1s  = sm;                // [128][260] floats
        float* hrow = sm + 33280;        // [2][256]
        float* red  = sm + 33792;        // [8]

        for (int i = tid; i < 8192; i += 256) {
            int h = i >> 6, k4 = i & 63;
            ((float4*)w1s)[h * 65 + k4] = ((const float4*)w1t)[i];
        }
        float w2v = w2[ho];
        float b1v = b1[ho];
        float b2v = b2[0];

        for (int t = 0; t <= 512; ++t) {
            if (t >= 1) {
                for (int i = tid; i < 512; i += 256) {
                    int bb = i >> 8, k = i & 255;
                    hrow[bb * 256 + k] =
                        __ldcg(hbuf + (t & 1) * 8192 + (m * 2 + bb) * 256 + k);
                }
                __syncthreads();

                float a = b1v;
                const float4* h4 = (const float4*)(hrow + bat * 256);
                const float4* w4 = (const float4*)(w1s + ho * 260);
#pragma unroll 16
                for (int kk = 0; kk < 64; kk++) {
                    float4 hv = h4[kk];
                    float4 wv = w4[kk];
                    a = fmaf(hv.x, wv.x, fmaf(hv.y, wv.y, fmaf(hv.z, wv.z, fmaf(hv.w, wv.w, a))));
                }
                float contrib = fmaxf(a, 0.f) * w2v;
#pragma unroll
                for (int o = 16; o > 0; o >>= 1)
                    contrib += __shfl_down_sync(0xffffffffu, contrib, o);
                if ((tid & 31) == 0) red[tid >> 5] = contrib;
                __syncthreads();
                if (tid == 0) {
                    int bidx = m * 2;
                    float pp = red[0] + red[1] + red[2] + red[3] + b2v;
                    out[bidx * 512 + (t - 1)] = pp * mask[bidx * 512 + (t - 1)];
                }
                if (tid == 128) {
                    int bidx = m * 2 + 1;
                    float pp = red[4] + red[5] + red[6] + red[7] + b2v;
                    out[bidx * 512 + (t - 1)] = pp * mask[bidx * 512 + (t - 1)];
                }
                __syncthreads();
            }
            if (t < 512) group_bar(syncArr, m, (unsigned)(t + 1) * 9u);
        }
    }
}

// ---------------------------------------------------------------------------
// Launcher
// ---------------------------------------------------------------------------
extern "C" void kernel_launch(void* const* d_in, const int* in_sizes, int n_in,
                              void* d_out, int out_size)
{
    const float* inputs   = (const float*)d_in[0];
    const float* mask     = (const float*)d_in[1];
    /* d_in[2] = lengths (unused) */
    const float* embed_w  = (const float*)d_in[3];
    const float* embed_b  = (const float*)d_in[4];
    const float* qkvo_w   = (const float*)d_in[5];
    const float* qkvo_b   = (const float*)d_in[6];
    const float* ln_g     = (const float*)d_in[7];
    const float* ln_b     = (const float*)d_in[8];
    const float* ff_w1    = (const float*)d_in[9];
    const float* ff_b1    = (const float*)d_in[10];
    const float* ff_w2    = (const float*)d_in[11];
    const float* ff_b2    = (const float*)d_in[12];
    const float* enc_ln_g = (const float*)d_in[13];
    const float* enc_ln_b = (const float*)d_in[14];
    const float* wih      = (const float*)d_in[15];
    const float* whh      = (const float*)d_in[16];
    const float* bih      = (const float*)d_in[17];
    const float* bhh      = (const float*)d_in[18];
    const float* dec_h0   = (const float*)d_in[19];
    const float* dec_c0   = (const float*)d_in[20];
    const float* out_w1   = (const float*)d_in[21];
    const float* out_b1   = (const float*)d_in[22];
    const float* out_w2   = (const float*)d_in[23];
    const float* out_b2   = (const float*)d_in[24];
    float* out = (float*)d_out;
    (void)in_sizes; (void)n_in; (void)out_size;

    float *px, *py, *pqkv, *po, *ph1, *ppre, *pinT, *pwtf, *pWET, *pWmR, *pw1t,
          *pg0, *pbt, *phb;
    unsigned* psync;
    cudaGetSymbolAddress((void**)&px,    g_x);
    cudaGetSymbolAddress((void**)&py,    g_y);
    cudaGetSymbolAddress((void**)&pqkv,  g_qkv);
    cudaGetSymbolAddress((void**)&po,    g_o);
    cudaGetSymbolAddress((void**)&ph1,   g_h1);
    cudaGetSymbolAddress((void**)&ppre,  g_pre);
    cudaGetSymbolAddress((void**)&pinT,  g_inT);
    cudaGetSymbolAddress((void**)&pwtf,  g_wtf);
    cudaGetSymbolAddress((void**)&pWET,  g_WihEncT);
    cudaGetSymbolAddress((void**)&pWmR,  g_WmR);
    cudaGetSymbolAddress((void**)&pw1t,  g_w1t);
    cudaGetSymbolAddress((void**)&pg0,   g_g0);
    cudaGetSymbolAddress((void**)&pbt,   g_biasTot);
    cudaGetSymbolAddress((void**)&phb,   g_hbuf);
    cudaGetSymbolAddress((void**)&psync, g_syncArr);

    cudaFuncSetAttribute(gemm_tc, cudaFuncAttributeMaxDynamicSharedMemorySize, GEMM_SMEM);
    cudaFuncSetAttribute(attn_tc, cudaFuncAttributeMaxDynamicSharedMemorySize, 110592);
    cudaFuncSetAttribute(lstm_persist_k, cudaFuncAttributeMaxDynamicSharedMemorySize, 137216);

    const int M = 16384;
    const long QKV_C = 16384L * 256;

    // prep: tf32 conversions + LSTM weights + barrier reset
    cvtw_k<<<19200, 256>>>(inputs, embed_w, qkvo_w, ff_w1, ff_w2, pinT, pwtf);
    lstm_prep_k<<<1024, 256>>>(wih, whh, bih, bhh, dec_h0, out_w1,
                               pWET, pWmR, pw1t, pg0, pbt, psync);

    // Embed (K=300)
    gemm_tc<<<dim3(2, 128), 256, GEMM_SMEM>>>(pinT, pwtf + OFF_EMB, embed_b,
                                              nullptr, px,
                                              M, 256, 300, 0, 0, 2, 0, 0, 0);

    // Transformer layers
    for (int l = 0; l < 6; l++) {
        const float* Wq = pwtf + OFF_QKVO + (size_t)(l * 4) * 65536;
        const float* Wo = pwtf + OFF_QKVO + (size_t)(l * 4 + 3) * 65536;
        const float* bq = qkvo_b + (l * 4) * 256;
        const float* bo = qkvo_b + (l * 4 + 3) * 256;

        layernorm_k<<<2048, 256>>>(px, ln_g + l * 512, ln_b + l * 512, py);
        gemm_tc<<<dim3(6, 128), 256, GEMM_SMEM>>>(py, Wq, bq, nullptr, pqkv,
                                                  M, 256, 256, 0, 1,
                                                  2, 65536, QKV_C, 256);
        attn_tc<<<dim3(4, 256), 256, 110592>>>(pqkv, pqkv + QKV_C,
                                               pqkv + 2 * QKV_C, mask, po);
        gemm_tc<<<dim3(2, 128), 256, GEMM_SMEM>>>(po, Wo, bo, px, px,
                                                  M, 256, 256, 0, 0, 2, 0, 0, 0);

        layernorm_k<<<2048, 256>>>(px, ln_g + l * 512 + 256, ln_b + l * 512 + 256, py);
        gemm_tc<<<dim3(1, 128), 256, GEMM_SMEM>>>(py, pwtf + OFF_FF1 + (size_t)l * 32768,
                                                  ff_b1 + l * 128, nullptr, ph1,
                                                  M, 128, 256, 1, 1, 1, 0, 0, 0);
        gemm_tc<<<dim3(2, 128), 256, GEMM_SMEM>>>(ph1, pwtf + OFF_FF2 + (size_t)l * 32768,
                                                  ff_b2 + l * 256, px, px,
                                                  M, 256, 128, 0, 0, 2, 0, 0, 0);
    }

    // Encoder LN -> enc (in py, tf32-rounded)
    layernorm_k<<<2048, 256>>>(px, enc_ln_g, enc_ln_b, py);

    // pre = enc @ wih[:,256:].T + (bih+bhh)
    gemm_tc<<<dim3(8, 128), 256, GEMM_SMEM>>>(py, pWET, pbt, nullptr, ppre,
                                              M, 1024, 256, 0, 0, 8, 0, 0, 0);

    // Persistent LSTM scan + output head (144 blocks, 16 independent groups)
    lstm_persist_k<<<144, 256, 137216>>>(ppre, pWmR, pw1t, pg0, dec_c0,
                                         out_b1, out_w2, out_b2, mask,
                                         phb, psync, out);
}